// round 1
// baseline (speedup 1.0000x reference)
#include <cuda_runtime.h>
#include <cuda_bf16.h>
#include <math.h>

// Problem constants
#define BB 16
#define CC 256
#define PP 20
#define KK 50
#define NPTS 1000          // P*K
#define KDIM 16384         // C*64  (fc1 input)
#define H1DIM 1024
#define MDIM 2000          // P*K*2
#define FDIM 258

// Output layout: refined [16*1000*2]=32000 @0, v [320] @32000, init [32000] @32320
#define OUT_V    32000
#define OUT_INIT 32320

// ---------------- scratch (device globals; no allocation) ----------------
__device__ float g_flat[BB * KDIM];                 // pooled, [b][k]
__device__ float g_hpart[16 * BB * H1DIM];          // fc1 partials [split][b][n]
__device__ float g_logpart[8 * BB * 2048];          // fc2 partials [split][b][m] (m padded 2048)
__device__ float g_feat[(size_t)BB * FDIM * 1024];  // [b][k(258)][pt padded 1024]; padding stays 0

// ---------------- 1) avg pool 32x32 -> 8x8 (4x4 windows) ----------------
__global__ void pool_kernel(const float* __restrict__ p4) {
    int idx = blockIdx.x * 256 + threadIdx.x;       // 0..262143 = b*16384 + c*64 + i*8 + j
    int j  = idx & 7;
    int i  = (idx >> 3) & 7;
    int bc = idx >> 6;                              // b*256 + c
    const float* base = p4 + (size_t)bc * 1024 + i * 128 + j * 4;
    float s = 0.f;
#pragma unroll
    for (int di = 0; di < 4; di++) {
        float4 v = *(const float4*)(base + di * 32);
        s += v.x + v.y + v.z + v.w;
    }
    g_flat[idx] = s * (1.0f / 16.0f);
}

// ---------------- 2) FC1: h = flat @ W1^T  (partials, 16 k-splits) ----------------
// grid (16 n-tiles of 64, 16 k-splits of 1024), 256 threads
__global__ void fc1_kernel(const float* __restrict__ W1) {
    __shared__ float sW[64][33];     // [n][kk], pad 33
    __shared__ float sflat[32][16];  // [kk][b]
    int tid = threadIdx.x;
    int n0 = blockIdx.x * 64;
    int k0 = blockIdx.y * 1024;
    int tn = tid & 63;
    int tb = tid >> 6;               // 0..3 -> batches tb*4..tb*4+3
    float a0 = 0.f, a1 = 0.f, a2 = 0.f, a3 = 0.f;

    for (int kc = 0; kc < 1024; kc += 32) {
        // W tile: 64 x 32, float4 loads, coalesced
#pragma unroll
        for (int t = 0; t < 2; t++) {
            int e = tid + t * 256;               // 0..511 float4 slots
            int r = e >> 3, c = e & 7;
            float4 v = *(const float4*)&W1[(size_t)(n0 + r) * KDIM + k0 + kc + c * 4];
            sW[r][c * 4 + 0] = v.x; sW[r][c * 4 + 1] = v.y;
            sW[r][c * 4 + 2] = v.z; sW[r][c * 4 + 3] = v.w;
        }
        // flat tile: 32 k x 16 b, stored [kk][b]
#pragma unroll
        for (int t = 0; t < 2; t++) {
            int e = tid + t * 256;               // 0..511
            int b = e >> 5, kk = e & 31;
            sflat[kk][b] = g_flat[b * KDIM + k0 + kc + kk];
        }
        __syncthreads();
#pragma unroll
        for (int kk = 0; kk < 32; kk++) {
            float w = sW[tn][kk];
            float4 f = *(const float4*)&sflat[kk][tb * 4];
            a0 += w * f.x; a1 += w * f.y; a2 += w * f.z; a3 += w * f.w;
        }
        __syncthreads();
    }
    int n = n0 + tn;
    float* dst = &g_hpart[(size_t)blockIdx.y * 16 * H1DIM];
    dst[(tb * 4 + 0) * H1DIM + n] = a0;
    dst[(tb * 4 + 1) * H1DIM + n] = a1;
    dst[(tb * 4 + 2) * H1DIM + n] = a2;
    dst[(tb * 4 + 3) * H1DIM + n] = a3;
}

// ---------------- 3) FC2: logits = relu(h+b1) @ W2^T (partials, 8 k-splits) ----------------
// grid (8 m-tiles of 256, 8 k-splits of 128), 256 threads
__global__ void fc2_kernel(const float* __restrict__ W2, const float* __restrict__ b1) {
    __shared__ float sh[128][16];        // [kk][b], relu(h) slice
    __shared__ float sW2[256 * 17];      // [m][kk chunk 16], pad 17
    int tid = threadIdx.x;
    int m0 = blockIdx.x * 256;
    int k0 = blockIdx.y * 128;

    // load + reduce h slice, apply bias+relu
#pragma unroll
    for (int t = 0; t < 8; t++) {
        int e = tid + t * 256;           // 0..2047
        int b = e >> 7, kk = e & 127;
        float s = b1[k0 + kk];
#pragma unroll
        for (int sp = 0; sp < 16; sp++) s += g_hpart[(sp * 16 + b) * H1DIM + k0 + kk];
        sh[kk][b] = fmaxf(s, 0.f);
    }

    int m = m0 + tid;
    float acc[16];
#pragma unroll
    for (int i = 0; i < 16; i++) acc[i] = 0.f;

    for (int kc = 0; kc < 128; kc += 16) {
        __syncthreads();
#pragma unroll
        for (int t = 0; t < 16; t++) {
            int e = tid + t * 256;       // 0..4095
            int r = e >> 4, c = e & 15;
            float w = 0.f;
            if (m0 + r < MDIM) w = W2[(size_t)(m0 + r) * H1DIM + k0 + kc + c];
            sW2[r * 17 + c] = w;
        }
        __syncthreads();
#pragma unroll
        for (int kk = 0; kk < 16; kk++) {
            float w = sW2[tid * 17 + kk];
#pragma unroll
            for (int b = 0; b < 16; b += 4) {
                float4 h4 = *(const float4*)&sh[kc + kk][b];
                acc[b + 0] += w * h4.x; acc[b + 1] += w * h4.y;
                acc[b + 2] += w * h4.z; acc[b + 3] += w * h4.w;
            }
        }
    }
    if (m < MDIM) {
        float* dst = &g_logpart[(size_t)blockIdx.y * 16 * 2048];
#pragma unroll
        for (int b = 0; b < 16; b++) dst[b * 2048 + m] = acc[b];
    }
}

// ---------------- 4) epilogue: sigmoid -> init_pts (d_out) + feat coord rows ----------------
__global__ void epi_kernel(const float* __restrict__ b2, float* __restrict__ out) {
    int idx = blockIdx.x * 256 + threadIdx.x;   // 0..31999
    int b = idx / MDIM, m = idx - b * MDIM;
    float s = b2[m];
#pragma unroll
    for (int sp = 0; sp < 8; sp++) s += g_logpart[(sp * 16 + b) * 2048 + m];
    float v = 1.f / (1.f + expf(-s));
    out[OUT_INIT + b * MDIM + m] = v;
    int pt = m >> 1, c = m & 1;
    g_feat[((size_t)b * FDIM + 256 + c) * 1024 + pt] = v;
}

// ---------------- 5) bilinear gather: one block per (b,c), image in SMEM ----------------
__global__ void gather_kernel(const float* __restrict__ p2, const float* __restrict__ out) {
    extern __shared__ float img[];               // 16384 floats = 64KB
    int bc = blockIdx.x;                          // b*256 + c
    int b = bc >> 8;
    int tid = threadIdx.x;
    const float4* src = (const float4*)(p2 + (size_t)bc * 16384);
    float4* di = (float4*)img;
#pragma unroll
    for (int t = 0; t < 16; t++) di[tid + t * 256] = src[tid + t * 256];
    __syncthreads();

    const float* initp = out + OUT_INIT + b * MDIM;
    float* frow = &g_feat[((size_t)b * FDIM + (bc & 255)) * 1024];
#pragma unroll
    for (int t = 0; t < 4; t++) {
        int pt = tid + t * 256;
        if (pt < NPTS) {
            float ix = initp[pt * 2 + 0];
            float iy = initp[pt * 2 + 1];
            float x = ix * 128.f - 0.5f;
            float y = iy * 128.f - 0.5f;
            float x0f = floorf(x), y0f = floorf(y);
            int x0 = (int)x0f, y0 = (int)y0f;
            float wx = x - x0f, wy = y - y0f;
            bool xv0 = (x0 >= 0) & (x0 <= 127);
            bool xv1 = (x0 + 1 >= 0) & (x0 + 1 <= 127);
            bool yv0 = (y0 >= 0) & (y0 <= 127);
            bool yv1 = (y0 + 1 >= 0) & (y0 + 1 <= 127);
            int x0c = min(max(x0, 0), 127), x1c = min(max(x0 + 1, 0), 127);
            int y0c = min(max(y0, 0), 127), y1c = min(max(y0 + 1, 0), 127);
            float v00 = (xv0 && yv0) ? img[y0c * 128 + x0c] : 0.f;
            float v10 = (xv1 && yv0) ? img[y0c * 128 + x1c] : 0.f;
            float v01 = (xv0 && yv1) ? img[y1c * 128 + x0c] : 0.f;
            float v11 = (xv1 && yv1) ? img[y1c * 128 + x1c] : 0.f;
            frow[pt] = v00 * (1.f - wx) * (1.f - wy) + v10 * wx * (1.f - wy)
                     + v01 * (1.f - wx) * wy        + v11 * wx * wy;
        }
    }
}

// ---------------- 6) refine MLP: 258->128->64->2, tanh, clip ----------------
// grid (21 pt-tiles of 48, 16 b), 256 threads, dynamic smem 92544 B
__global__ void refine_kernel(const float* __restrict__ R1, const float* __restrict__ rb1,
                              const float* __restrict__ R2, const float* __restrict__ rb2,
                              const float* __restrict__ R3, const float* __restrict__ rb3,
                              float* __restrict__ out) {
    extern __shared__ float sm[];
    float* sfeat = sm;                    // 258*48 = 12384  (reused later: sR2T 8192 + sh2 64*52)
    float* sR1t  = sm + 12384;            // 32*128 = 4096
    float* sh1   = sm + 12384 + 4096;     // 128*52 = 6656

    int tid = threadIdx.x;
    int b = blockIdx.y;
    int p0 = blockIdx.x * 48;

    // load feat tile [258][48]  (padded pts read zeros)
    for (int e = tid; e < FDIM * 48; e += 256) {
        int kr = e / 48, pp = e - kr * 48;
        sfeat[kr * 48 + pp] = g_feat[((size_t)b * FDIM + kr) * 1024 + p0 + pp];
    }
    __syncthreads();

    // ---- layer 1 ----
    int n = tid & 127, g = tid >> 7;
    int q0 = g * 24;
    float acc[24];
#pragma unroll
    for (int j = 0; j < 24; j++) acc[j] = 0.f;

    for (int kc = 0; kc < 256; kc += 32) {
        __syncthreads();
#pragma unroll
        for (int t = 0; t < 16; t++) {
            int e = tid + t * 256;        // 0..4095
            int nr = e >> 5, kk = e & 31;
            sR1t[kk * 128 + nr] = R1[nr * FDIM + kc + kk];
        }
        __syncthreads();
#pragma unroll
        for (int kk = 0; kk < 32; kk++) {
            float w = sR1t[kk * 128 + n];
            const float4* fr = (const float4*)&sfeat[(kc + kk) * 48 + q0];
#pragma unroll
            for (int j = 0; j < 6; j++) {
                float4 f = fr[j];
                acc[j * 4 + 0] += w * f.x; acc[j * 4 + 1] += w * f.y;
                acc[j * 4 + 2] += w * f.z; acc[j * 4 + 3] += w * f.w;
            }
        }
    }
    // coord features k = 256, 257
    {
        float w0 = R1[n * FDIM + 256];
        float w1 = R1[n * FDIM + 257];
        const float4* f0 = (const float4*)&sfeat[256 * 48 + q0];
        const float4* f1 = (const float4*)&sfeat[257 * 48 + q0];
#pragma unroll
        for (int j = 0; j < 6; j++) {
            float4 a = f0[j], c = f1[j];
            acc[j * 4 + 0] += w0 * a.x + w1 * c.x; acc[j * 4 + 1] += w0 * a.y + w1 * c.y;
            acc[j * 4 + 2] += w0 * a.z + w1 * c.z; acc[j * 4 + 3] += w0 * a.w + w1 * c.w;
        }
    }
    float bias1 = rb1[n];
#pragma unroll
    for (int j = 0; j < 24; j++) sh1[n * 52 + q0 + j] = fmaxf(acc[j] + bias1, 0.f);
    __syncthreads();

    // ---- layer 2 ---- (reuse sfeat region)
    float* sR2T = sm;                     // [kk 128][n 64]
    float* sh2  = sm + 128 * 64;          // [k 64][pt 52]
#pragma unroll
    for (int t = 0; t < 32; t++) {
        int e = tid + t * 256;            // 0..8191
        int nr = e >> 7, kk = e & 127;
        sR2T[kk * 64 + nr] = R2[nr * 128 + kk];
    }
    __syncthreads();

    int n2 = tid & 63, g2 = tid >> 6;
    int q2 = g2 * 12;
    float acc2[12];
#pragma unroll
    for (int j = 0; j < 12; j++) acc2[j] = 0.f;
#pragma unroll 4
    for (int kk = 0; kk < 128; kk++) {
        float w = sR2T[kk * 64 + n2];
        const float4* hr = (const float4*)&sh1[kk * 52 + q2];
#pragma unroll
        for (int j = 0; j < 3; j++) {
            float4 f = hr[j];
            acc2[j * 4 + 0] += w * f.x; acc2[j * 4 + 1] += w * f.y;
            acc2[j * 4 + 2] += w * f.z; acc2[j * 4 + 3] += w * f.w;
        }
    }
    float bias2 = rb2[n2];
#pragma unroll
    for (int j = 0; j < 12; j++) sh2[n2 * 52 + q2 + j] = fmaxf(acc2[j] + bias2, 0.f);
    __syncthreads();

    // ---- layer 3: 2 outputs per point ----
    if (tid < 96) {
        int c = tid / 48, pp = tid - (tid / 48) * 48;
        float a = rb3[c];
#pragma unroll 8
        for (int k = 0; k < 64; k++) a += sh2[k * 52 + pp] * R3[c * 64 + k];
        float disp = tanhf(a);
        int ptg = p0 + pp;
        if (ptg < NPTS) {
            float iv = out[OUT_INIT + b * MDIM + ptg * 2 + c];
            float r = fminf(fmaxf(iv + 0.1f * disp, 0.f), 1.f);
            out[(b * NPTS + ptg) * 2 + c] = r;
        }
    }
}

// ---------------- 7) value head: sigmoid(relu(pf@V1^T+vb1)@V2^T+vb2) ----------------
// grid 320 (b*20+p), 128 threads, dynamic smem 52112 B
__global__ void value_kernel(const float* __restrict__ V1, const float* __restrict__ vb1,
                             const float* __restrict__ V2, const float* __restrict__ vb2,
                             float* __restrict__ out) {
    extern __shared__ float sv[];
    float* spf  = sv;            // 100
    float* sV1  = sv + 128;      // 12800
    float* sred = sv + 128 + 12800;  // 128
    int bp = blockIdx.x;
    int tid = threadIdx.x;
    if (tid < 100) spf[tid] = out[bp * 100 + tid];
    const float4* v4 = (const float4*)V1;
    float4* s4 = (float4*)sV1;
#pragma unroll
    for (int t = 0; t < 25; t++) s4[tid + t * 128] = v4[tid + t * 128];
    __syncthreads();
    float a = vb1[tid];
#pragma unroll 4
    for (int k = 0; k < 100; k++) a += spf[k] * sV1[tid * 100 + k];
    sred[tid] = fmaxf(a, 0.f) * V2[tid];
    __syncthreads();
#pragma unroll
    for (int s = 64; s > 0; s >>= 1) {
        if (tid < s) sred[tid] += sred[tid + s];
        __syncthreads();
    }
    if (tid == 0) out[OUT_V + bp] = 1.f / (1.f + expf(-(sred[0] + vb2[0])));
}

// ---------------- launch ----------------
extern "C" void kernel_launch(void* const* d_in, const int* in_sizes, int n_in,
                              void* d_out, int out_size) {
    const float* p4   = (const float*)d_in[0];
    const float* p2   = (const float*)d_in[1];
    // d_in[2] = segmentation (unused by reference)
    const float* W1   = (const float*)d_in[3];
    const float* b1   = (const float*)d_in[4];
    const float* W2   = (const float*)d_in[5];
    const float* b2   = (const float*)d_in[6];
    const float* R1   = (const float*)d_in[7];
    const float* rb1  = (const float*)d_in[8];
    const float* R2   = (const float*)d_in[9];
    const float* rb2  = (const float*)d_in[10];
    const float* R3   = (const float*)d_in[11];
    const float* rb3  = (const float*)d_in[12];
    const float* V1   = (const float*)d_in[13];
    const float* vb1  = (const float*)d_in[14];
    const float* V2   = (const float*)d_in[15];
    const float* vb2  = (const float*)d_in[16];
    float* out = (float*)d_out;

    cudaFuncSetAttribute(gather_kernel, cudaFuncAttributeMaxDynamicSharedMemorySize, 65536);
    cudaFuncSetAttribute(refine_kernel, cudaFuncAttributeMaxDynamicSharedMemorySize, 92544);
    cudaFuncSetAttribute(value_kernel,  cudaFuncAttributeMaxDynamicSharedMemorySize, 52224);

    pool_kernel<<<1024, 256>>>(p4);
    fc1_kernel<<<dim3(16, 16), 256>>>(W1);
    fc2_kernel<<<dim3(8, 8), 256>>>(W2, b1);
    epi_kernel<<<125, 256>>>(b2, out);
    gather_kernel<<<4096, 256, 65536>>>(p2, out);
    refine_kernel<<<dim3(21, 16), 256, 92544>>>(R1, rb1, R2, rb2, R3, rb3, out);
    value_kernel<<<320, 128, 52224>>>(V1, vb1, V2, vb2, out);
}

// round 2
// speedup vs baseline: 1.0096x; 1.0096x over previous
#include <cuda_runtime.h>
#include <cuda_bf16.h>
#include <math.h>

// Problem constants
#define BB 16
#define CC 256
#define PP 20
#define KK 50
#define NPTS 1000          // P*K
#define KDIM 16384         // C*64  (fc1 input)
#define H1DIM 1024
#define MDIM 2000          // P*K*2
#define FDIM 258

// Output layout: refined [16*1000*2]=32000 @0, v [320] @32000, init [32000] @32320
#define OUT_V    32000
#define OUT_INIT 32320

// ---------------- packed f32x2 helpers (SASS FFMA2 path) ----------------
typedef unsigned long long u64p;

__device__ __forceinline__ u64p pack2(float lo, float hi) {
    u64p r; asm("mov.b64 %0, {%1,%2};" : "=l"(r) : "f"(lo), "f"(hi)); return r;
}
__device__ __forceinline__ float2 unpack2(u64p v) {
    float2 r; asm("mov.b64 {%0,%1}, %2;" : "=f"(r.x), "=f"(r.y) : "l"(v)); return r;
}
#define FMA2(d, a, b, c) asm("fma.rn.f32x2 %0, %1, %2, %3;" : "=l"(d) : "l"(a), "l"(b), "l"(c))

// ---------------- scratch (device globals; no allocation) ----------------
__device__ float g_flat[BB * KDIM];                 // pooled, [b][k]
__device__ float g_hpart[32 * BB * H1DIM];          // fc1 partials [split][b][n]
__device__ float g_h[BB * H1DIM];                   // relu(h) [b][n]
__device__ float g_logpart[8 * BB * 2048];          // fc2 partials [split][b][m] (m padded 2048)
__device__ float g_feat[(size_t)BB * FDIM * 1024];  // [b][k(258)][pt padded 1024]; padding stays 0

// ---------------- 1) avg pool 32x32 -> 8x8 (4x4 windows) ----------------
__global__ void pool_kernel(const float* __restrict__ p4) {
    int idx = blockIdx.x * 256 + threadIdx.x;       // 0..262143 = b*16384 + c*64 + i*8 + j
    int j  = idx & 7;
    int i  = (idx >> 3) & 7;
    int bc = idx >> 6;                              // b*256 + c
    const float* base = p4 + (size_t)bc * 1024 + i * 128 + j * 4;
    float s = 0.f;
#pragma unroll
    for (int di = 0; di < 4; di++) {
        float4 v = *(const float4*)(base + di * 32);
        s += v.x + v.y + v.z + v.w;
    }
    g_flat[idx] = s * (1.0f / 16.0f);
}

// ---------------- 2) FC1: h = flat @ W1^T  (partials, 32 k-splits) ----------------
// grid (16 n-tiles of 64, 32 k-splits of 512), 256 threads
__global__ void fc1_kernel(const float* __restrict__ W1) {
    __shared__ float sW[64][33];     // [n][kk], pad 33
    __shared__ float sflat[32][16];  // [kk][b]
    int tid = threadIdx.x;
    int n0 = blockIdx.x * 64;
    int k0 = blockIdx.y * 512;
    int tn = tid & 63;
    int tb = tid >> 6;               // 0..3 -> batches tb*4..tb*4+3
    u64p a01 = 0, a23 = 0;

    for (int kc = 0; kc < 512; kc += 32) {
        // W tile: 64 x 32, float4 loads, coalesced
#pragma unroll
        for (int t = 0; t < 2; t++) {
            int e = tid + t * 256;               // 0..511 float4 slots
            int r = e >> 3, c = e & 7;
            float4 v = *(const float4*)&W1[(size_t)(n0 + r) * KDIM + k0 + kc + c * 4];
            sW[r][c * 4 + 0] = v.x; sW[r][c * 4 + 1] = v.y;
            sW[r][c * 4 + 2] = v.z; sW[r][c * 4 + 3] = v.w;
        }
        // flat tile: 32 k x 16 b, stored [kk][b]
#pragma unroll
        for (int t = 0; t < 2; t++) {
            int e = tid + t * 256;               // 0..511
            int b = e >> 5, kk = e & 31;
            sflat[kk][b] = g_flat[b * KDIM + k0 + kc + kk];
        }
        __syncthreads();
#pragma unroll
        for (int kk = 0; kk < 32; kk++) {
            u64p w2 = pack2(sW[tn][kk], sW[tn][kk]);
            ulonglong2 f = *(const ulonglong2*)&sflat[kk][tb * 4];
            FMA2(a01, f.x, w2, a01);
            FMA2(a23, f.y, w2, a23);
        }
        __syncthreads();
    }
    int n = n0 + tn;
    float2 v01 = unpack2(a01), v23 = unpack2(a23);
    float* dst = &g_hpart[(size_t)blockIdx.y * 16 * H1DIM];
    dst[(tb * 4 + 0) * H1DIM + n] = v01.x;
    dst[(tb * 4 + 1) * H1DIM + n] = v01.y;
    dst[(tb * 4 + 2) * H1DIM + n] = v23.x;
    dst[(tb * 4 + 3) * H1DIM + n] = v23.y;
}

// ---------------- 2b) reduce partials -> relu(h + b1) ----------------
__global__ void reduce_h_kernel(const float* __restrict__ b1) {
    int idx = blockIdx.x * 256 + threadIdx.x;   // 0..16383 = b*1024 + n
    int n = idx & 1023;
    float s = b1[n];
#pragma unroll
    for (int sp = 0; sp < 32; sp++) s += g_hpart[sp * (BB * H1DIM) + idx];
    g_h[idx] = fmaxf(s, 0.f);
}

// ---------------- 3) FC2: logits = relu_h @ W2^T (partials, 8 k-splits) ----------------
// grid (8 m-tiles of 256, 8 k-splits of 128), 256 threads
__global__ void fc2_kernel(const float* __restrict__ W2) {
    __shared__ float sh[128][16];        // [kk][b]
    __shared__ float sW2[256 * 17];      // [m][kk chunk 16], pad 17
    int tid = threadIdx.x;
    int m0 = blockIdx.x * 256;
    int k0 = blockIdx.y * 128;

    // load relu(h) slice
#pragma unroll
    for (int t = 0; t < 8; t++) {
        int e = tid + t * 256;           // 0..2047
        int b = e >> 7, kk = e & 127;
        sh[kk][b] = g_h[b * H1DIM + k0 + kk];
    }

    int m = m0 + tid;
    u64p acc[8];
#pragma unroll
    for (int i = 0; i < 8; i++) acc[i] = 0;

    for (int kc = 0; kc < 128; kc += 16) {
        __syncthreads();
#pragma unroll
        for (int t = 0; t < 16; t++) {
            int e = tid + t * 256;       // 0..4095
            int r = e >> 4, c = e & 15;
            float w = 0.f;
            if (m0 + r < MDIM) w = W2[(size_t)(m0 + r) * H1DIM + k0 + kc + c];
            sW2[r * 17 + c] = w;
        }
        __syncthreads();
#pragma unroll
        for (int kk = 0; kk < 16; kk++) {
            u64p w2 = pack2(sW2[tid * 17 + kk], sW2[tid * 17 + kk]);
#pragma unroll
            for (int b = 0; b < 16; b += 8) {
                ulonglong2 h4a = *(const ulonglong2*)&sh[kc + kk][b];
                ulonglong2 h4b = *(const ulonglong2*)&sh[kc + kk][b + 4];
                FMA2(acc[b / 2 + 0], h4a.x, w2, acc[b / 2 + 0]);
                FMA2(acc[b / 2 + 1], h4a.y, w2, acc[b / 2 + 1]);
                FMA2(acc[b / 2 + 2], h4b.x, w2, acc[b / 2 + 2]);
                FMA2(acc[b / 2 + 3], h4b.y, w2, acc[b / 2 + 3]);
            }
        }
    }
    if (m < MDIM) {
        float* dst = &g_logpart[(size_t)blockIdx.y * 16 * 2048];
#pragma unroll
        for (int i = 0; i < 8; i++) {
            float2 v = unpack2(acc[i]);
            dst[(i * 2 + 0) * 2048 + m] = v.x;
            dst[(i * 2 + 1) * 2048 + m] = v.y;
        }
    }
}

// ---------------- 4) epilogue: sigmoid -> init_pts (d_out) + feat coord rows ----------------
__global__ void epi_kernel(const float* __restrict__ b2, float* __restrict__ out) {
    int idx = blockIdx.x * 256 + threadIdx.x;   // 0..31999
    int b = idx / MDIM, m = idx - b * MDIM;
    float s = b2[m];
#pragma unroll
    for (int sp = 0; sp < 8; sp++) s += g_logpart[(sp * 16 + b) * 2048 + m];
    float v = 1.f / (1.f + expf(-s));
    out[OUT_INIT + b * MDIM + m] = v;
    int pt = m >> 1, c = m & 1;
    g_feat[((size_t)b * FDIM + 256 + c) * 1024 + pt] = v;
}

// ---------------- 5) bilinear gather: one block per (b,c), image in SMEM ----------------
__global__ void gather_kernel(const float* __restrict__ p2, const float* __restrict__ out) {
    extern __shared__ float img[];               // 16384 floats = 64KB
    int bc = blockIdx.x;                          // b*256 + c
    int b = bc >> 8;
    int tid = threadIdx.x;
    const float4* src = (const float4*)(p2 + (size_t)bc * 16384);
    float4* di = (float4*)img;
#pragma unroll
    for (int t = 0; t < 16; t++) di[tid + t * 256] = src[tid + t * 256];
    __syncthreads();

    const float* initp = out + OUT_INIT + b * MDIM;
    float* frow = &g_feat[((size_t)b * FDIM + (bc & 255)) * 1024];
#pragma unroll
    for (int t = 0; t < 4; t++) {
        int pt = tid + t * 256;
        if (pt < NPTS) {
            float ix = initp[pt * 2 + 0];
            float iy = initp[pt * 2 + 1];
            float x = ix * 128.f - 0.5f;
            float y = iy * 128.f - 0.5f;
            float x0f = floorf(x), y0f = floorf(y);
            int x0 = (int)x0f, y0 = (int)y0f;
            float wx = x - x0f, wy = y - y0f;
            bool xv0 = (x0 >= 0) & (x0 <= 127);
            bool xv1 = (x0 + 1 >= 0) & (x0 + 1 <= 127);
            bool yv0 = (y0 >= 0) & (y0 <= 127);
            bool yv1 = (y0 + 1 >= 0) & (y0 + 1 <= 127);
            int x0c = min(max(x0, 0), 127), x1c = min(max(x0 + 1, 0), 127);
            int y0c = min(max(y0, 0), 127), y1c = min(max(y0 + 1, 0), 127);
            float v00 = (xv0 && yv0) ? img[y0c * 128 + x0c] : 0.f;
            float v10 = (xv1 && yv0) ? img[y0c * 128 + x1c] : 0.f;
            float v01 = (xv0 && yv1) ? img[y1c * 128 + x0c] : 0.f;
            float v11 = (xv1 && yv1) ? img[y1c * 128 + x1c] : 0.f;
            frow[pt] = v00 * (1.f - wx) * (1.f - wy) + v10 * wx * (1.f - wy)
                     + v01 * (1.f - wx) * wy        + v11 * wx * wy;
        }
    }
}

// ---------------- 6) refine MLP: 258->128->64->2, tanh, clip ----------------
// grid (21 pt-tiles of 48, 16 b), 256 threads, dynamic smem 92544 B
__global__ void refine_kernel(const float* __restrict__ R1, const float* __restrict__ rb1,
                              const float* __restrict__ R2, const float* __restrict__ rb2,
                              const float* __restrict__ R3, const float* __restrict__ rb3,
                              float* __restrict__ out) {
    extern __shared__ float sm[];
    float* sfeat = sm;                    // 258*48 = 12384  (reused later: sR2T 8192 + sh2 64*52)
    float* sR1t  = sm + 12384;            // 32*128 = 4096
    float* sh1   = sm + 12384 + 4096;     // 128*52 = 6656

    int tid = threadIdx.x;
    int b = blockIdx.y;
    int p0 = blockIdx.x * 48;

    // load feat tile [258][48]  (padded pts read zeros)
    for (int e = tid; e < FDIM * 48; e += 256) {
        int kr = e / 48, pp = e - kr * 48;
        sfeat[kr * 48 + pp] = g_feat[((size_t)b * FDIM + kr) * 1024 + p0 + pp];
    }
    __syncthreads();

    // ---- layer 1 ----
    int n = tid & 127, g = tid >> 7;
    int q0 = g * 24;
    u64p acc[12];
#pragma unroll
    for (int j = 0; j < 12; j++) acc[j] = 0;

    for (int kc = 0; kc < 256; kc += 32) {
        __syncthreads();
#pragma unroll
        for (int t = 0; t < 16; t++) {
            int e = tid + t * 256;        // 0..4095
            int nr = e >> 5, kk = e & 31;
            sR1t[kk * 128 + nr] = R1[nr * FDIM + kc + kk];
        }
        __syncthreads();
#pragma unroll
        for (int kk = 0; kk < 32; kk++) {
            float w = sR1t[kk * 128 + n];
            u64p w2 = pack2(w, w);
            const ulonglong2* fr = (const ulonglong2*)&sfeat[(kc + kk) * 48 + q0];
#pragma unroll
            for (int j = 0; j < 6; j++) {
                ulonglong2 f = fr[j];
                FMA2(acc[j * 2 + 0], f.x, w2, acc[j * 2 + 0]);
                FMA2(acc[j * 2 + 1], f.y, w2, acc[j * 2 + 1]);
            }
        }
    }
    // coord features k = 256, 257
    {
        u64p w0 = pack2(R1[n * FDIM + 256], R1[n * FDIM + 256]);
        u64p w1 = pack2(R1[n * FDIM + 257], R1[n * FDIM + 257]);
        const ulonglong2* f0 = (const ulonglong2*)&sfeat[256 * 48 + q0];
        const ulonglong2* f1 = (const ulonglong2*)&sfeat[257 * 48 + q0];
#pragma unroll
        for (int j = 0; j < 6; j++) {
            ulonglong2 a = f0[j], c = f1[j];
            FMA2(acc[j * 2 + 0], a.x, w0, acc[j * 2 + 0]);
            FMA2(acc[j * 2 + 1], a.y, w0, acc[j * 2 + 1]);
            FMA2(acc[j * 2 + 0], c.x, w1, acc[j * 2 + 0]);
            FMA2(acc[j * 2 + 1], c.y, w1, acc[j * 2 + 1]);
        }
    }
    float bias1 = rb1[n];
#pragma unroll
    for (int j = 0; j < 12; j++) {
        float2 v = unpack2(acc[j]);
        sh1[n * 52 + q0 + j * 2 + 0] = fmaxf(v.x + bias1, 0.f);
        sh1[n * 52 + q0 + j * 2 + 1] = fmaxf(v.y + bias1, 0.f);
    }
    __syncthreads();

    // ---- layer 2 ---- (reuse sfeat region)
    float* sR2T = sm;                     // [kk 128][n 64]
    float* sh2  = sm + 128 * 64;          // [k 64][pt 52]
#pragma unroll
    for (int t = 0; t < 32; t++) {
        int e = tid + t * 256;            // 0..8191
        int nr = e >> 7, kk = e & 127;
        sR2T[kk * 64 + nr] = R2[nr * 128 + kk];
    }
    __syncthreads();

    int n2 = tid & 63, g2 = tid >> 6;
    int q2 = g2 * 12;
    u64p acc2[6];
#pragma unroll
    for (int j = 0; j < 6; j++) acc2[j] = 0;
#pragma unroll 4
    for (int kk = 0; kk < 128; kk++) {
        float w = sR2T[kk * 64 + n2];
        u64p w2 = pack2(w, w);
        const ulonglong2* hr = (const ulonglong2*)&sh1[kk * 52 + q2];
#pragma unroll
        for (int j = 0; j < 3; j++) {
            ulonglong2 f = hr[j];
            FMA2(acc2[j * 2 + 0], f.x, w2, acc2[j * 2 + 0]);
            FMA2(acc2[j * 2 + 1], f.y, w2, acc2[j * 2 + 1]);
        }
    }
    float bias2 = rb2[n2];
#pragma unroll
    for (int j = 0; j < 6; j++) {
        float2 v = unpack2(acc2[j]);
        sh2[n2 * 52 + q2 + j * 2 + 0] = fmaxf(v.x + bias2, 0.f);
        sh2[n2 * 52 + q2 + j * 2 + 1] = fmaxf(v.y + bias2, 0.f);
    }
    __syncthreads();

    // ---- layer 3: 2 outputs per point ----
    if (tid < 96) {
        int c = tid / 48, pp = tid - (tid / 48) * 48;
        float a = rb3[c];
#pragma unroll 8
        for (int k = 0; k < 64; k++) a += sh2[k * 52 + pp] * R3[c * 64 + k];
        float disp = tanhf(a);
        int ptg = p0 + pp;
        if (ptg < NPTS) {
            float iv = out[OUT_INIT + b * MDIM + ptg * 2 + c];
            float r = fminf(fmaxf(iv + 0.1f * disp, 0.f), 1.f);
            out[(b * NPTS + ptg) * 2 + c] = r;
        }
    }
}

// ---------------- 7) value head: sigmoid(relu(pf@V1^T+vb1)@V2^T+vb2) ----------------
// grid 320 (b*20+p), 128 threads, dynamic smem 52224 B
__global__ void value_kernel(const float* __restrict__ V1, const float* __restrict__ vb1,
                             const float* __restrict__ V2, const float* __restrict__ vb2,
                             float* __restrict__ out) {
    extern __shared__ float sv[];
    float* spf  = sv;            // 100
    float* sV1  = sv + 128;      // 12800
    float* sred = sv + 128 + 12800;  // 128
    int bp = blockIdx.x;
    int tid = threadIdx.x;
    if (tid < 100) spf[tid] = out[bp * 100 + tid];
    const float4* v4 = (const float4*)V1;
    float4* s4 = (float4*)sV1;
#pragma unroll
    for (int t = 0; t < 25; t++) s4[tid + t * 128] = v4[tid + t * 128];
    __syncthreads();
    float a = vb1[tid];
#pragma unroll 4
    for (int k = 0; k < 100; k++) a += spf[k] * sV1[tid * 100 + k];
    sred[tid] = fmaxf(a, 0.f) * V2[tid];
    __syncthreads();
#pragma unroll
    for (int s = 64; s > 0; s >>= 1) {
        if (tid < s) sred[tid] += sred[tid + s];
        __syncthreads();
    }
    if (tid == 0) out[OUT_V + bp] = 1.f / (1.f + expf(-(sred[0] + vb2[0])));
}

// ---------------- launch ----------------
extern "C" void kernel_launch(void* const* d_in, const int* in_sizes, int n_in,
                              void* d_out, int out_size) {
    const float* p4   = (const float*)d_in[0];
    const float* p2   = (const float*)d_in[1];
    // d_in[2] = segmentation (unused by reference)
    const float* W1   = (const float*)d_in[3];
    const float* b1   = (const float*)d_in[4];
    const float* W2   = (const float*)d_in[5];
    const float* b2   = (const float*)d_in[6];
    const float* R1   = (const float*)d_in[7];
    const float* rb1  = (const float*)d_in[8];
    const float* R2   = (const float*)d_in[9];
    const float* rb2  = (const float*)d_in[10];
    const float* R3   = (const float*)d_in[11];
    const float* rb3  = (const float*)d_in[12];
    const float* V1   = (const float*)d_in[13];
    const float* vb1  = (const float*)d_in[14];
    const float* V2   = (const float*)d_in[15];
    const float* vb2  = (const float*)d_in[16];
    float* out = (float*)d_out;

    cudaFuncSetAttribute(gather_kernel, cudaFuncAttributeMaxDynamicSharedMemorySize, 65536);
    cudaFuncSetAttribute(refine_kernel, cudaFuncAttributeMaxDynamicSharedMemorySize, 92544);
    cudaFuncSetAttribute(value_kernel,  cudaFuncAttributeMaxDynamicSharedMemorySize, 52224);

    pool_kernel<<<1024, 256>>>(p4);
    fc1_kernel<<<dim3(16, 32), 256>>>(W1);
    reduce_h_kernel<<<64, 256>>>(b1);
    fc2_kernel<<<dim3(8, 8), 256>>>(W2);
    epi_kernel<<<125, 256>>>(b2, out);
    gather_kernel<<<4096, 256, 65536>>>(p2, out);
    refine_kernel<<<dim3(21, 16), 256, 92544>>>(R1, rb1, R2, rb2, R3, rb3, out);
    value_kernel<<<320, 128, 52224>>>(V1, vb1, V2, vb2, out);
}

// round 3
// speedup vs baseline: 1.6574x; 1.6416x over previous
#include <cuda_runtime.h>
#include <cuda_bf16.h>
#include <math.h>

// Problem constants
#define BB 16
#define PP 20
#define KK 50
#define NPTS 1000
#define KDIM 16384         // C*64 (fc1 input)
#define H1DIM 1024
#define MDIM 2000          // P*K*2
#define FDIM 258

// Output layout: refined [32000] @0, v [320] @32000, init [32000] @32320
#define OUT_V    32000
#define OUT_INIT 32320

// ---------------- packed f32x2 helpers (SASS FFMA2 path) ----------------
typedef unsigned long long u64p;
__device__ __forceinline__ u64p pack2(float lo, float hi) {
    u64p r; asm("mov.b64 %0, {%1,%2};" : "=l"(r) : "f"(lo), "f"(hi)); return r;
}
__device__ __forceinline__ float2 unpack2(u64p v) {
    float2 r; asm("mov.b64 {%0,%1}, %2;" : "=f"(r.x), "=f"(r.y) : "l"(v)); return r;
}
#define FMA2(d, a, b, c) asm("fma.rn.f32x2 %0, %1, %2, %3;" : "=l"(d) : "l"(a), "l"(b), "l"(c))

// ---------------- scratch ----------------
__device__ float g_flat[BB * KDIM];                    // pooled [b][k]
__device__ float g_hpart[128 * BB * H1DIM];            // fc1 partials [ks][b][n]
__device__ float g_h[BB * H1DIM];                      // relu(h) [b][n]
__device__ float g_logpart[32 * BB * 2048];            // fc2 partials [ks][b][m pad 2048]
__device__ float g_feat[(size_t)BB * FDIM * 1024];     // [b][k(258)][pt pad 1024]; pad zeros
__device__ float g_R1t[FDIM * 128];                    // R1 transposed [k][n]
__device__ float g_R2t[128 * 64];                      // R2 transposed [k][n]

// ---------------- 0) prep: transpose R1, R2 ----------------
__global__ void prep_kernel(const float* __restrict__ R1, const float* __restrict__ R2) {
    int idx = blockIdx.x * 256 + threadIdx.x;
    if (idx < FDIM * 128) {
        int k = idx >> 7, n = idx & 127;
        g_R1t[idx] = R1[n * FDIM + k];
    } else if (idx < FDIM * 128 + 128 * 64) {
        int i = idx - FDIM * 128;
        int k = i >> 6, n = i & 63;
        g_R2t[i] = R2[n * 128 + k];
    }
}

// ---------------- 1) avg pool 32x32 -> 8x8 ----------------
__global__ void pool_kernel(const float* __restrict__ p4) {
    int idx = blockIdx.x * 256 + threadIdx.x;
    int j = idx & 7, i = (idx >> 3) & 7;
    int bc = idx >> 6;
    const float* base = p4 + (size_t)bc * 1024 + i * 128 + j * 4;
    float s = 0.f;
#pragma unroll
    for (int di = 0; di < 4; di++) {
        float4 v = *(const float4*)(base + di * 32);
        s += v.x + v.y + v.z + v.w;
    }
    g_flat[idx] = s * (1.0f / 16.0f);
}

// ---------------- 2) FC1: all n per block, 128 k-splits ----------------
// grid 128, block 256. thread: 4n x 16b. smem 144384 B dynamic.
#define FC1_SW_STRIDE 33
#define FC1_SF_STRIDE 18
__global__ void fc1_kernel(const float* __restrict__ W1) {
    extern __shared__ float sm1[];
    float* sW = sm1;                       // [1024 n][33]
    float* sf = sm1 + 1024 * FC1_SW_STRIDE; // [128 k][18]
    int tid = threadIdx.x;
    int ks = blockIdx.x;
    int k0 = ks * 128;
    int n0 = tid * 4;

    // load flat slice [128 k][16 b], coalesced global, padded STS
#pragma unroll
    for (int t = 0; t < 8; t++) {
        int e = tid + t * 256;            // 0..2047
        int b = e >> 7, kk = e & 127;
        sf[kk * FC1_SF_STRIDE + b] = g_flat[b * KDIM + k0 + kk];
    }

    u64p acc[4][8];
#pragma unroll
    for (int r = 0; r < 4; r++)
#pragma unroll
        for (int j = 0; j < 8; j++) acc[r][j] = 0;

    for (int kc = 0; kc < 128; kc += 32) {
        __syncthreads();
        // load W chunk [1024 n][32 k] -> sW[n][kk] (row pad 33)
#pragma unroll
        for (int t = 0; t < 32; t++) {
            int f = tid + t * 256;         // float4 index, 0..8191
            int n = f >> 3, c = f & 7;
            float4 v = *(const float4*)&W1[(size_t)n * KDIM + k0 + kc + c * 4];
            float* d = &sW[n * FC1_SW_STRIDE + c * 4];
            d[0] = v.x; d[1] = v.y; d[2] = v.z; d[3] = v.w;
        }
        __syncthreads();
#pragma unroll 4
        for (int kk = 0; kk < 32; kk++) {
            u64p w2[4];
#pragma unroll
            for (int r = 0; r < 4; r++) {
                float w = sW[(n0 + r) * FC1_SW_STRIDE + kk];
                w2[r] = pack2(w, w);
            }
            const u64p* fl = (const u64p*)&sf[(kc + kk) * FC1_SF_STRIDE];
#pragma unroll
            for (int j = 0; j < 8; j++) {
                u64p f = fl[j];
#pragma unroll
                for (int r = 0; r < 4; r++) FMA2(acc[r][j], f, w2[r], acc[r][j]);
            }
        }
    }
    // store partials [ks][b][n]
#pragma unroll
    for (int r = 0; r < 4; r++)
#pragma unroll
        for (int j = 0; j < 8; j++) {
            float2 v = unpack2(acc[r][j]);
            g_hpart[(ks * 16 + 2 * j + 0) * H1DIM + n0 + r] = v.x;
            g_hpart[(ks * 16 + 2 * j + 1) * H1DIM + n0 + r] = v.y;
        }
}

// ---------------- 2b) reduce 128 partials -> relu(h+b1) ----------------
__global__ void reduce_h_kernel(const float* __restrict__ b1) {
    int idx = blockIdx.x * 256 + threadIdx.x;   // b*1024 + n
    int n = idx & 1023;
    float s = b1[n];
#pragma unroll 8
    for (int sp = 0; sp < 128; sp++) s += g_hpart[sp * (BB * H1DIM) + idx];
    g_h[idx] = fmaxf(s, 0.f);
}

// ---------------- 3) FC2: 512 m-tile x 32 k-slice, grid (4,32) ----------------
// thread: 2m x 16b. smem 67840 B dynamic.
#define FC2_SH_STRIDE 18
__global__ void fc2_kernel(const float* __restrict__ W2) {
    extern __shared__ float sm2[];
    float* sWt = sm2;                      // [32 k][512 m]
    float* sh  = sm2 + 32 * 512;           // [32 k][18]
    int tid = threadIdx.x;
    int m0 = blockIdx.x * 512;
    int ks = blockIdx.y;
    int k0 = ks * 32;
    int m = m0 + tid * 2;

    // h slice [32 k][16 b]
    if (tid < 128) {
        int e = tid;
#pragma unroll
        for (int t = 0; t < 4; t++, e += 128) {
            int b = e >> 5, kk = e & 31;
            sh[kk * FC2_SH_STRIDE + b] = g_h[b * H1DIM + k0 + kk];
        }
    }
    // W2 tile transposed: sWt[kk][m_local]
#pragma unroll
    for (int mi = 0; mi < 2; mi++) {
        int mr = m + mi;
        if (mr < MDIM) {
#pragma unroll
            for (int c = 0; c < 8; c++) {
                float4 v = *(const float4*)&W2[(size_t)mr * H1DIM + k0 + c * 4];
                sWt[(c * 4 + 0) * 512 + tid * 2 + mi] = v.x;
                sWt[(c * 4 + 1) * 512 + tid * 2 + mi] = v.y;
                sWt[(c * 4 + 2) * 512 + tid * 2 + mi] = v.z;
                sWt[(c * 4 + 3) * 512 + tid * 2 + mi] = v.w;
            }
        } else {
#pragma unroll
            for (int kk = 0; kk < 32; kk++) sWt[kk * 512 + tid * 2 + mi] = 0.f;
        }
    }
    __syncthreads();

    u64p acc[2][8];
#pragma unroll
    for (int mi = 0; mi < 2; mi++)
#pragma unroll
        for (int j = 0; j < 8; j++) acc[mi][j] = 0;

#pragma unroll 4
    for (int kk = 0; kk < 32; kk++) {
        float w0 = sWt[kk * 512 + tid * 2 + 0];
        float w1 = sWt[kk * 512 + tid * 2 + 1];
        u64p w20 = pack2(w0, w0), w21 = pack2(w1, w1);
        const u64p* fl = (const u64p*)&sh[kk * FC2_SH_STRIDE];
#pragma unroll
        for (int j = 0; j < 8; j++) {
            u64p f = fl[j];
            FMA2(acc[0][j], f, w20, acc[0][j]);
            FMA2(acc[1][j], f, w21, acc[1][j]);
        }
    }
#pragma unroll
    for (int mi = 0; mi < 2; mi++) {
        int mr = m + mi;
        if (mr < MDIM) {
#pragma unroll
            for (int j = 0; j < 8; j++) {
                float2 v = unpack2(acc[mi][j]);
                g_logpart[(ks * 16 + 2 * j + 0) * 2048 + mr] = v.x;
                g_logpart[(ks * 16 + 2 * j + 1) * 2048 + mr] = v.y;
            }
        }
    }
}

// ---------------- 4) epilogue: sigmoid -> init_pts + feat coord rows ----------------
__global__ void epi_kernel(const float* __restrict__ b2, float* __restrict__ out) {
    int idx = blockIdx.x * 256 + threadIdx.x;   // 0..31999
    int b = idx / MDIM, m = idx - b * MDIM;
    float s = b2[m];
#pragma unroll
    for (int sp = 0; sp < 32; sp++) s += g_logpart[(sp * 16 + b) * 2048 + m];
    float v = 1.f / (1.f + expf(-s));
    out[OUT_INIT + b * MDIM + m] = v;
    int pt = m >> 1, c = m & 1;
    g_feat[((size_t)b * FDIM + 256 + c) * 1024 + pt] = v;
}

// ---------------- 5) bilinear gather ----------------
__global__ void gather_kernel(const float* __restrict__ p2, const float* __restrict__ out) {
    extern __shared__ float img[];               // 64KB
    int bc = blockIdx.x;
    int b = bc >> 8;
    int tid = threadIdx.x;

    // prefetch point coords first (overlaps with image load)
    const float* initp = out + OUT_INIT + b * MDIM;
    float px[4], py[4];
#pragma unroll
    for (int t = 0; t < 4; t++) {
        int pt = tid + t * 256;
        if (pt < NPTS) { px[t] = initp[pt * 2 + 0]; py[t] = initp[pt * 2 + 1]; }
    }

    const float4* src = (const float4*)(p2 + (size_t)bc * 16384);
    float4* di = (float4*)img;
#pragma unroll
    for (int t = 0; t < 16; t++) di[tid + t * 256] = src[tid + t * 256];
    __syncthreads();

    float* frow = &g_feat[((size_t)b * FDIM + (bc & 255)) * 1024];
#pragma unroll
    for (int t = 0; t < 4; t++) {
        int pt = tid + t * 256;
        if (pt < NPTS) {
            float x = px[t] * 128.f - 0.5f;
            float y = py[t] * 128.f - 0.5f;
            float x0f = floorf(x), y0f = floorf(y);
            int x0 = (int)x0f, y0 = (int)y0f;
            float wx = x - x0f, wy = y - y0f;
            bool xv0 = (x0 >= 0) & (x0 <= 127);
            bool xv1 = (x0 + 1 >= 0) & (x0 + 1 <= 127);
            bool yv0 = (y0 >= 0) & (y0 <= 127);
            bool yv1 = (y0 + 1 >= 0) & (y0 + 1 <= 127);
            int x0c = min(max(x0, 0), 127), x1c = min(max(x0 + 1, 0), 127);
            int y0c = min(max(y0, 0), 127), y1c = min(max(y0 + 1, 0), 127);
            float v00 = (xv0 && yv0) ? img[y0c * 128 + x0c] : 0.f;
            float v10 = (xv1 && yv0) ? img[y0c * 128 + x1c] : 0.f;
            float v01 = (xv0 && yv1) ? img[y1c * 128 + x0c] : 0.f;
            float v11 = (xv1 && yv1) ? img[y1c * 128 + x1c] : 0.f;
            frow[pt] = v00 * (1.f - wx) * (1.f - wy) + v10 * wx * (1.f - wy)
                     + v01 * (1.f - wx) * wy        + v11 * wx * wy;
        }
    }
}

// ---------------- 6) refine MLP: 64-pt tiles, register tiled ----------------
// grid (16, 16), 256 threads, smem 115200 B dynamic.
__global__ void refine_kernel(const float* __restrict__ rb1,
                              const float* __restrict__ rb2,
                              const float* __restrict__ R3, const float* __restrict__ rb3,
                              float* __restrict__ out) {
    extern __shared__ float smr[];
    float* sfeat = smr;                           // [258][64] = 66048 B
    float* sR1   = smr + FDIM * 64;               // [32][128] = 16384 B
    float* sh1   = smr + FDIM * 64 + 32 * 128;    // [128][64] = 32768 B
    // layer-2 reuse of sfeat region:
    float* sR2t  = smr;                           // [128][64] = 32768 B
    float* sh2   = smr + 128 * 64;                // [64][64]  = 16384 B
    float* sR3   = smr + 128 * 64 + 64 * 64;      // [128]

    int tid = threadIdx.x;
    int b = blockIdx.y;
    int p0 = blockIdx.x * 64;
    int pg = tid & 15;           // 16 pt-groups of 4
    int ng = tid >> 4;           // 16 n-groups

    // load feat tile [258][64]
    for (int e = tid; e < FDIM * 64; e += 256) {
        int kr = e >> 6, pp = e & 63;
        sfeat[kr * 64 + pp] = g_feat[((size_t)b * FDIM + kr) * 1024 + p0 + pp];
    }

    // ---- layer 1: thread = 8n x 4pt ----
    int n0 = ng * 8;
    u64p acc[8][2];
#pragma unroll
    for (int r = 0; r < 8; r++) { acc[r][0] = 0; acc[r][1] = 0; }

    for (int kc = 0; kc < 256; kc += 32) {
        __syncthreads();
#pragma unroll
        for (int t = 0; t < 4; t++) {
            int f = tid + t * 256;        // float4 idx 0..1023
            ((float4*)sR1)[f] = ((const float4*)(g_R1t + kc * 128))[f];
        }
        __syncthreads();
#pragma unroll 2
        for (int kk = 0; kk < 32; kk++) {
            u64p w2[8];
#pragma unroll
            for (int r = 0; r < 8; r += 4) {
                float4 w4 = *(const float4*)&sR1[kk * 128 + n0 + r];
                w2[r + 0] = pack2(w4.x, w4.x); w2[r + 1] = pack2(w4.y, w4.y);
                w2[r + 2] = pack2(w4.z, w4.z); w2[r + 3] = pack2(w4.w, w4.w);
            }
            ulonglong2 f = *(const ulonglong2*)&sfeat[(kc + kk) * 64 + pg * 4];
#pragma unroll
            for (int r = 0; r < 8; r++) {
                FMA2(acc[r][0], f.x, w2[r], acc[r][0]);
                FMA2(acc[r][1], f.y, w2[r], acc[r][1]);
            }
        }
    }
    // coord rows k = 256, 257
#pragma unroll
    for (int kr = 256; kr < 258; kr++) {
        ulonglong2 f = *(const ulonglong2*)&sfeat[kr * 64 + pg * 4];
#pragma unroll
        for (int r = 0; r < 8; r++) {
            float w = g_R1t[kr * 128 + n0 + r];
            u64p w2 = pack2(w, w);
            FMA2(acc[r][0], f.x, w2, acc[r][0]);
            FMA2(acc[r][1], f.y, w2, acc[r][1]);
        }
    }
#pragma unroll
    for (int r = 0; r < 8; r++) {
        float bias = rb1[n0 + r];
        float2 v0 = unpack2(acc[r][0]), v1 = unpack2(acc[r][1]);
        float* d = &sh1[(n0 + r) * 64 + pg * 4];
        // sh1 is outside the reused region; safe to write before sync
        d[0] = fmaxf(v0.x + bias, 0.f); d[1] = fmaxf(v0.y + bias, 0.f);
        d[2] = fmaxf(v1.x + bias, 0.f); d[3] = fmaxf(v1.y + bias, 0.f);
    }
    __syncthreads();

    // ---- layer 2: thread = 4n x 4pt ---- (sR2t/sh2 overlay sfeat region)
#pragma unroll
    for (int t = 0; t < 8; t++) {
        int f = tid + t * 256;            // float4 idx 0..2047
        ((float4*)sR2t)[f] = ((const float4*)g_R2t)[f];
    }
    if (tid < 128) sR3[tid] = R3[tid];
    __syncthreads();

    int n2 = ng * 4;
    u64p acc2[4][2];
#pragma unroll
    for (int r = 0; r < 4; r++) { acc2[r][0] = 0; acc2[r][1] = 0; }
#pragma unroll 2
    for (int kk = 0; kk < 128; kk++) {
        float4 w4 = *(const float4*)&sR2t[kk * 64 + n2];
        u64p w2[4] = { pack2(w4.x, w4.x), pack2(w4.y, w4.y),
                       pack2(w4.z, w4.z), pack2(w4.w, w4.w) };
        ulonglong2 f = *(const ulonglong2*)&sh1[kk * 64 + pg * 4];
#pragma unroll
        for (int r = 0; r < 4; r++) {
            FMA2(acc2[r][0], f.x, w2[r], acc2[r][0]);
            FMA2(acc2[r][1], f.y, w2[r], acc2[r][1]);
        }
    }
    __syncthreads();   // done reading sR2t region before sh2 writes? sh2 is within region too
#pragma unroll
    for (int r = 0; r < 4; r++) {
        float bias = rb2[n2 + r];
        float2 v0 = unpack2(acc2[r][0]), v1 = unpack2(acc2[r][1]);
        float* d = &sh2[(n2 + r) * 64 + pg * 4];
        d[0] = fmaxf(v0.x + bias, 0.f); d[1] = fmaxf(v0.y + bias, 0.f);
        d[2] = fmaxf(v1.x + bias, 0.f); d[3] = fmaxf(v1.y + bias, 0.f);
    }
    __syncthreads();

    // ---- layer 3 ----
    if (tid < 128) {
        int c = tid >> 6, pp = tid & 63;
        float a = rb3[c];
#pragma unroll 8
        for (int k = 0; k < 64; k++) a += sh2[k * 64 + pp] * sR3[c * 64 + k];
        float disp = tanhf(a);
        int ptg = p0 + pp;
        if (ptg < NPTS) {
            float iv = out[OUT_INIT + b * MDIM + ptg * 2 + c];
            float r = fminf(fmaxf(iv + 0.1f * disp, 0.f), 1.f);
            out[(b * NPTS + ptg) * 2 + c] = r;
        }
    }
}

// ---------------- 7) value head ----------------
__global__ void value_kernel(const float* __restrict__ V1, const float* __restrict__ vb1,
                             const float* __restrict__ V2, const float* __restrict__ vb2,
                             float* __restrict__ out) {
    extern __shared__ float sv[];
    float* spf  = sv;                // 100
    float* sV1  = sv + 128;          // 12800
    float* sred = sv + 128 + 12800;  // 128
    int bp = blockIdx.x;
    int tid = threadIdx.x;
    if (tid < 100) spf[tid] = out[bp * 100 + tid];
    const float4* v4 = (const float4*)V1;
    float4* s4 = (float4*)sV1;
#pragma unroll
    for (int t = 0; t < 25; t++) s4[tid + t * 128] = v4[tid + t * 128];
    __syncthreads();
    float a = vb1[tid];
#pragma unroll 4
    for (int k = 0; k < 100; k++) a += spf[k] * sV1[tid * 100 + k];
    sred[tid] = fmaxf(a, 0.f) * V2[tid];
    __syncthreads();
#pragma unroll
    for (int s = 64; s > 0; s >>= 1) {
        if (tid < s) sred[tid] += sred[tid + s];
        __syncthreads();
    }
    if (tid == 0) out[OUT_V + bp] = 1.f / (1.f + expf(-(sred[0] + vb2[0])));
}

// ---------------- launch ----------------
extern "C" void kernel_launch(void* const* d_in, const int* in_sizes, int n_in,
                              void* d_out, int out_size) {
    const float* p4   = (const float*)d_in[0];
    const float* p2   = (const float*)d_in[1];
    const float* W1   = (const float*)d_in[3];
    const float* b1   = (const float*)d_in[4];
    const float* W2   = (const float*)d_in[5];
    const float* b2   = (const float*)d_in[6];
    const float* R1   = (const float*)d_in[7];
    const float* rb1  = (const float*)d_in[8];
    const float* R2   = (const float*)d_in[9];
    const float* rb2  = (const float*)d_in[10];
    const float* R3   = (const float*)d_in[11];
    const float* rb3  = (const float*)d_in[12];
    const float* V1   = (const float*)d_in[13];
    const float* vb1  = (const float*)d_in[14];
    const float* V2   = (const float*)d_in[15];
    const float* vb2  = (const float*)d_in[16];
    float* out = (float*)d_out;

    const int FC1_SMEM = (1024 * FC1_SW_STRIDE + 128 * FC1_SF_STRIDE) * 4;  // 144384
    const int FC2_SMEM = (32 * 512 + 32 * FC2_SH_STRIDE) * 4;               // 67840
    const int RFN_SMEM = (FDIM * 64 + 32 * 128 + 128 * 64) * 4;             // 115200

    cudaFuncSetAttribute(fc1_kernel,    cudaFuncAttributeMaxDynamicSharedMemorySize, FC1_SMEM);
    cudaFuncSetAttribute(fc2_kernel,    cudaFuncAttributeMaxDynamicSharedMemorySize, FC2_SMEM);
    cudaFuncSetAttribute(gather_kernel, cudaFuncAttributeMaxDynamicSharedMemorySize, 65536);
    cudaFuncSetAttribute(refine_kernel, cudaFuncAttributeMaxDynamicSharedMemorySize, RFN_SMEM);
    cudaFuncSetAttribute(value_kernel,  cudaFuncAttributeMaxDynamicSharedMemorySize, 52224);

    prep_kernel<<<162, 256>>>(R1, R2);
    pool_kernel<<<1024, 256>>>(p4);
    fc1_kernel<<<128, 256, FC1_SMEM>>>(W1);
    reduce_h_kernel<<<64, 256>>>(b1);
    fc2_kernel<<<dim3(4, 32), 256, FC2_SMEM>>>(W2);
    epi_kernel<<<125, 256>>>(b2, out);
    gather_kernel<<<4096, 256, 65536>>>(p2, out);
    refine_kernel<<<dim3(16, 16), 256, RFN_SMEM>>>(rb1, rb2, R3, rb3, out);
    value_kernel<<<320, 128, 52224>>>(V1, vb1, V2, vb2, out);
}

// round 4
// speedup vs baseline: 1.8493x; 1.1157x over previous
#include <cuda_runtime.h>
#include <cuda_bf16.h>
#include <math.h>

// Problem constants
#define BB 16
#define NPTS 1000
#define KDIM 16384         // C*64 (fc1 input)
#define H1DIM 1024
#define MDIM 2000          // P*K*2
#define FDIM 258

// Output layout: refined [32000] @0, v [320] @32000, init [32000] @32320
#define OUT_V    32000
#define OUT_INIT 32320

// ---------------- packed f32x2 helpers (SASS FFMA2 path) ----------------
typedef unsigned long long u64p;
__device__ __forceinline__ u64p pack2(float lo, float hi) {
    u64p r; asm("mov.b64 %0, {%1,%2};" : "=l"(r) : "f"(lo), "f"(hi)); return r;
}
__device__ __forceinline__ float2 unpack2(u64p v) {
    float2 r; asm("mov.b64 {%0,%1}, %2;" : "=f"(r.x), "=f"(r.y) : "l"(v)); return r;
}
#define FMA2(d, a, b, c) asm("fma.rn.f32x2 %0, %1, %2, %3;" : "=l"(d) : "l"(a), "l"(b), "l"(c))

// ---------------- scratch ----------------
__device__ float g_flat[BB * KDIM];                    // pooled [b][k]
__device__ float g_hpart[128 * BB * H1DIM];            // fc1 partials [ks][b][n]
__device__ float g_h[BB * H1DIM];                      // relu(h) [b][n]
__device__ float g_logpart[32 * BB * 2048];            // fc2 partials [ks][b][m pad]
__device__ float g_feat[(size_t)BB * FDIM * 1024];     // [b][k(258)][pt pad 1024]
__device__ float g_R1t[FDIM * 128];                    // R1^T [k][n]
__device__ float g_R2t[128 * 64];                      // R2^T [k][n]

// ---------------- 1) avg pool (+ prep transposes merged) ----------------
__global__ void pool_kernel(const float* __restrict__ p4,
                            const float* __restrict__ R1, const float* __restrict__ R2) {
    if (blockIdx.x < 1024) {
        int idx = blockIdx.x * 256 + threadIdx.x;
        int j = idx & 7, i = (idx >> 3) & 7;
        int bc = idx >> 6;
        const float* base = p4 + (size_t)bc * 1024 + i * 128 + j * 4;
        float s = 0.f;
#pragma unroll
        for (int di = 0; di < 4; di++) {
            float4 v = *(const float4*)(base + di * 32);
            s += v.x + v.y + v.z + v.w;
        }
        g_flat[idx] = s * (1.0f / 16.0f);
    } else {
        int idx = (blockIdx.x - 1024) * 256 + threadIdx.x;
        if (idx < FDIM * 128) {
            int k = idx >> 7, n = idx & 127;
            g_R1t[idx] = R1[n * FDIM + k];
        } else if (idx < FDIM * 128 + 128 * 64) {
            int i = idx - FDIM * 128;
            int k = i >> 6, n = i & 63;
            g_R2t[i] = R2[n * 128 + k];
        }
    }
}

// ---------------- 2) FC1: 512 n x 128 k-slice per block, grid (128,2) ----------------
// thread: rows {tid, tid+256} x 16b. smem 76800 B.
#define FC1_SW_STRIDE 33
#define FC1_SF_STRIDE 18
__global__ void fc1_kernel(const float* __restrict__ W1) {
    extern __shared__ float sm1[];
    float* sW = sm1;                         // [512 n][33]
    float* sf = sm1 + 512 * FC1_SW_STRIDE;   // [128 k][18]
    int tid = threadIdx.x;
    int ks = blockIdx.x;
    int k0 = ks * 128;
    int nb = blockIdx.y * 512;

    // flat slice [128 k][16 b]
#pragma unroll
    for (int t = 0; t < 8; t++) {
        int e = tid + t * 256;
        int b = e >> 7, kk = e & 127;
        sf[kk * FC1_SF_STRIDE + b] = g_flat[b * KDIM + k0 + kk];
    }

    u64p acc[2][8];
#pragma unroll
    for (int r = 0; r < 2; r++)
#pragma unroll
        for (int j = 0; j < 8; j++) acc[r][j] = 0;

    for (int kc = 0; kc < 128; kc += 32) {
        __syncthreads();
        // W chunk [512 n][32 k]
#pragma unroll
        for (int t = 0; t < 16; t++) {
            int f = tid + t * 256;           // float4 idx 0..4095
            int r = f >> 3, c = f & 7;
            float4 v = *(const float4*)&W1[(size_t)(nb + r) * KDIM + k0 + kc + c * 4];
            float* d = &sW[r * FC1_SW_STRIDE + c * 4];
            d[0] = v.x; d[1] = v.y; d[2] = v.z; d[3] = v.w;
        }
        __syncthreads();
#pragma unroll 4
        for (int kk = 0; kk < 32; kk++) {
            float w0 = sW[tid * FC1_SW_STRIDE + kk];
            float w1 = sW[(tid + 256) * FC1_SW_STRIDE + kk];
            u64p w20 = pack2(w0, w0), w21 = pack2(w1, w1);
            const u64p* fl = (const u64p*)&sf[(kc + kk) * FC1_SF_STRIDE];
#pragma unroll
            for (int j = 0; j < 8; j++) {
                u64p f = fl[j];
                FMA2(acc[0][j], f, w20, acc[0][j]);
                FMA2(acc[1][j], f, w21, acc[1][j]);
            }
        }
    }
#pragma unroll
    for (int r = 0; r < 2; r++) {
        int n = nb + tid + r * 256;
#pragma unroll
        for (int j = 0; j < 8; j++) {
            float2 v = unpack2(acc[r][j]);
            g_hpart[(ks * 16 + 2 * j + 0) * H1DIM + n] = v.x;
            g_hpart[(ks * 16 + 2 * j + 1) * H1DIM + n] = v.y;
        }
    }
}

// ---------------- 2b) reduce 128 partials: 8 lanes/elem + shuffle ----------------
__global__ void reduce_h_kernel(const float* __restrict__ b1) {
    int gid = blockIdx.x * 256 + threadIdx.x;   // 0..131071
    int e = gid >> 3;                            // 0..16383 = b*1024+n
    int r = gid & 7;
    float s = 0.f;
#pragma unroll
    for (int t = 0; t < 16; t++) s += g_hpart[(r + t * 8) * (BB * H1DIM) + e];
    s += __shfl_xor_sync(0xFFFFFFFFu, s, 1);
    s += __shfl_xor_sync(0xFFFFFFFFu, s, 2);
    s += __shfl_xor_sync(0xFFFFFFFFu, s, 4);
    if (r == 0) g_h[e] = fmaxf(s + b1[e & 1023], 0.f);
}

// ---------------- 3) FC2: 512 m-tile x 32 k-slice, grid (4,32) ----------------
#define FC2_SH_STRIDE 18
__global__ void fc2_kernel(const float* __restrict__ W2) {
    extern __shared__ float sm2[];
    float* sWt = sm2;                      // [32 k][512 m]
    float* sh  = sm2 + 32 * 512;           // [32 k][18]
    int tid = threadIdx.x;
    int m0 = blockIdx.x * 512;
    int ks = blockIdx.y;
    int k0 = ks * 32;
    int m = m0 + tid * 2;

    if (tid < 128) {
        int e = tid;
#pragma unroll
        for (int t = 0; t < 4; t++, e += 128) {
            int b = e >> 5, kk = e & 31;
            sh[kk * FC2_SH_STRIDE + b] = g_h[b * H1DIM + k0 + kk];
        }
    }
#pragma unroll
    for (int mi = 0; mi < 2; mi++) {
        int mr = m + mi;
        if (mr < MDIM) {
#pragma unroll
            for (int c = 0; c < 8; c++) {
                float4 v = *(const float4*)&W2[(size_t)mr * H1DIM + k0 + c * 4];
                sWt[(c * 4 + 0) * 512 + tid * 2 + mi] = v.x;
                sWt[(c * 4 + 1) * 512 + tid * 2 + mi] = v.y;
                sWt[(c * 4 + 2) * 512 + tid * 2 + mi] = v.z;
                sWt[(c * 4 + 3) * 512 + tid * 2 + mi] = v.w;
            }
        } else {
#pragma unroll
            for (int kk = 0; kk < 32; kk++) sWt[kk * 512 + tid * 2 + mi] = 0.f;
        }
    }
    __syncthreads();

    u64p acc[2][8];
#pragma unroll
    for (int mi = 0; mi < 2; mi++)
#pragma unroll
        for (int j = 0; j < 8; j++) acc[mi][j] = 0;

#pragma unroll 4
    for (int kk = 0; kk < 32; kk++) {
        float w0 = sWt[kk * 512 + tid * 2 + 0];
        float w1 = sWt[kk * 512 + tid * 2 + 1];
        u64p w20 = pack2(w0, w0), w21 = pack2(w1, w1);
        const u64p* fl = (const u64p*)&sh[kk * FC2_SH_STRIDE];
#pragma unroll
        for (int j = 0; j < 8; j++) {
            u64p f = fl[j];
            FMA2(acc[0][j], f, w20, acc[0][j]);
            FMA2(acc[1][j], f, w21, acc[1][j]);
        }
    }
#pragma unroll
    for (int mi = 0; mi < 2; mi++) {
        int mr = m + mi;
        if (mr < MDIM) {
#pragma unroll
            for (int j = 0; j < 8; j++) {
                float2 v = unpack2(acc[mi][j]);
                g_logpart[(ks * 16 + 2 * j + 0) * 2048 + mr] = v.x;
                g_logpart[(ks * 16 + 2 * j + 1) * 2048 + mr] = v.y;
            }
        }
    }
}

// ---------------- 4) epilogue: shuffle-reduce 32 partials -> sigmoid ----------------
__global__ void epi_kernel(const float* __restrict__ b2, float* __restrict__ out) {
    int gid = blockIdx.x * 256 + threadIdx.x;   // 0..255999
    int e = gid >> 3;                            // 0..31999
    int r = gid & 7;
    int b = e / MDIM, m = e - b * MDIM;
    float s = 0.f;
#pragma unroll
    for (int t = 0; t < 4; t++) s += g_logpart[((r + t * 8) * 16 + b) * 2048 + m];
    s += __shfl_xor_sync(0xFFFFFFFFu, s, 1);
    s += __shfl_xor_sync(0xFFFFFFFFu, s, 2);
    s += __shfl_xor_sync(0xFFFFFFFFu, s, 4);
    if (r == 0) {
        float v = 1.f / (1.f + expf(-(s + b2[m])));
        out[OUT_INIT + b * MDIM + m] = v;
        int pt = m >> 1, c = m & 1;
        g_feat[((size_t)b * FDIM + 256 + c) * 1024 + pt] = v;
    }
}

// ---------------- 5) bilinear gather ----------------
__global__ void gather_kernel(const float* __restrict__ p2, const float* __restrict__ out) {
    extern __shared__ float img[];               // 64KB
    int bc = blockIdx.x;
    int b = bc >> 8;
    int tid = threadIdx.x;

    const float* initp = out + OUT_INIT + b * MDIM;
    float px[4], py[4];
#pragma unroll
    for (int t = 0; t < 4; t++) {
        int pt = tid + t * 256;
        if (pt < NPTS) { px[t] = initp[pt * 2 + 0]; py[t] = initp[pt * 2 + 1]; }
    }

    const float4* src = (const float4*)(p2 + (size_t)bc * 16384);
    float4* di = (float4*)img;
#pragma unroll
    for (int t = 0; t < 16; t++) di[tid + t * 256] = src[tid + t * 256];
    __syncthreads();

    float* frow = &g_feat[((size_t)b * FDIM + (bc & 255)) * 1024];
#pragma unroll
    for (int t = 0; t < 4; t++) {
        int pt = tid + t * 256;
        if (pt < NPTS) {
            float x = px[t] * 128.f - 0.5f;
            float y = py[t] * 128.f - 0.5f;
            float x0f = floorf(x), y0f = floorf(y);
            int x0 = (int)x0f, y0 = (int)y0f;
            float wx = x - x0f, wy = y - y0f;
            bool xv0 = (x0 >= 0) & (x0 <= 127);
            bool xv1 = (x0 + 1 >= 0) & (x0 + 1 <= 127);
            bool yv0 = (y0 >= 0) & (y0 <= 127);
            bool yv1 = (y0 + 1 >= 0) & (y0 + 1 <= 127);
            int x0c = min(max(x0, 0), 127), x1c = min(max(x0 + 1, 0), 127);
            int y0c = min(max(y0, 0), 127), y1c = min(max(y0 + 1, 0), 127);
            float v00 = (xv0 && yv0) ? img[y0c * 128 + x0c] : 0.f;
            float v10 = (xv1 && yv0) ? img[y0c * 128 + x1c] : 0.f;
            float v01 = (xv0 && yv1) ? img[y1c * 128 + x0c] : 0.f;
            float v11 = (xv1 && yv1) ? img[y1c * 128 + x1c] : 0.f;
            frow[pt] = v00 * (1.f - wx) * (1.f - wy) + v10 * wx * (1.f - wy)
                     + v01 * (1.f - wx) * wy        + v11 * wx * wy;
        }
    }
}

// ---------------- 6) refine MLP: streamed k-chunks, 82432 B smem ----------------
// smem float offsets:
//   sh1   @0      [128][64]                  (persists layer1->2)
//   sfeatc@8192   [32][64]     (layer1)      | sR2t @8192  [128][64] (layer2)
//   sR1   @10240  [32][128]    (layer1)      | sh2  @16384 [64][64]
//   scoord@14336  [2][64]      (layer1)      | sR3  @20480 [128]
__global__ void refine_kernel(const float* __restrict__ rb1,
                              const float* __restrict__ rb2,
                              const float* __restrict__ R3, const float* __restrict__ rb3,
                              float* __restrict__ out) {
    extern __shared__ float smr[];
    float* sh1    = smr;
    float* sfeatc = smr + 8192;
    float* sR1    = smr + 10240;
    float* scoord = smr + 14336;
    float* sR2t   = smr + 8192;
    float* sh2    = smr + 16384;
    float* sR3    = smr + 20480;

    int tid = threadIdx.x;
    int b = blockIdx.y;
    int p0 = blockIdx.x * 64;
    int pg = tid & 15;           // 16 pt-groups of 4
    int ng = tid >> 4;           // 16 n-groups
    int n0 = ng * 8;

    // coord rows (k=256,257)
    if (tid < 128)
        scoord[tid] = g_feat[((size_t)b * FDIM + 256 + (tid >> 6)) * 1024 + p0 + (tid & 63)];

    u64p acc[8][2];
#pragma unroll
    for (int r = 0; r < 8; r++) { acc[r][0] = 0; acc[r][1] = 0; }

    for (int kc = 0; kc < 256; kc += 32) {
        __syncthreads();
        // feat chunk [32][64]: 512 float4
#pragma unroll
        for (int t = 0; t < 2; t++) {
            int f = tid + t * 256;
            int row = f >> 4, col = f & 15;
            ((float4*)sfeatc)[row * 16 + col] =
                *(const float4*)&g_feat[((size_t)b * FDIM + kc + row) * 1024 + p0 + col * 4];
        }
        // R1 chunk [32][128]: 1024 float4
#pragma unroll
        for (int t = 0; t < 4; t++) {
            int f = tid + t * 256;
            ((float4*)sR1)[f] = ((const float4*)(g_R1t + kc * 128))[f];
        }
        __syncthreads();
#pragma unroll 2
        for (int kk = 0; kk < 32; kk++) {
            u64p w2[8];
#pragma unroll
            for (int r = 0; r < 8; r += 4) {
                float4 w4 = *(const float4*)&sR1[kk * 128 + n0 + r];
                w2[r + 0] = pack2(w4.x, w4.x); w2[r + 1] = pack2(w4.y, w4.y);
                w2[r + 2] = pack2(w4.z, w4.z); w2[r + 3] = pack2(w4.w, w4.w);
            }
            ulonglong2 f = *(const ulonglong2*)&sfeatc[kk * 64 + pg * 4];
#pragma unroll
            for (int r = 0; r < 8; r++) {
                FMA2(acc[r][0], f.x, w2[r], acc[r][0]);
                FMA2(acc[r][1], f.y, w2[r], acc[r][1]);
            }
        }
    }
    // coord contributions
#pragma unroll
    for (int kr = 0; kr < 2; kr++) {
        ulonglong2 f = *(const ulonglong2*)&scoord[kr * 64 + pg * 4];
#pragma unroll
        for (int r = 0; r < 8; r++) {
            float w = g_R1t[(256 + kr) * 128 + n0 + r];
            u64p w2 = pack2(w, w);
            FMA2(acc[r][0], f.x, w2, acc[r][0]);
            FMA2(acc[r][1], f.y, w2, acc[r][1]);
        }
    }
#pragma unroll
    for (int r = 0; r < 8; r++) {
        float bias = rb1[n0 + r];
        float2 v0 = unpack2(acc[r][0]), v1 = unpack2(acc[r][1]);
        float* d = &sh1[(n0 + r) * 64 + pg * 4];
        d[0] = fmaxf(v0.x + bias, 0.f); d[1] = fmaxf(v0.y + bias, 0.f);
        d[2] = fmaxf(v1.x + bias, 0.f); d[3] = fmaxf(v1.y + bias, 0.f);
    }
    __syncthreads();

    // ---- layer 2 ---- (sR2t overlays layer-1 staging)
#pragma unroll
    for (int t = 0; t < 8; t++) {
        int f = tid + t * 256;
        ((float4*)sR2t)[f] = ((const float4*)g_R2t)[f];
    }
    if (tid < 128) sR3[tid] = R3[tid];
    __syncthreads();

    int n2 = ng * 4;
    u64p acc2[4][2];
#pragma unroll
    for (int r = 0; r < 4; r++) { acc2[r][0] = 0; acc2[r][1] = 0; }
#pragma unroll 2
    for (int kk = 0; kk < 128; kk++) {
        float4 w4 = *(const float4*)&sR2t[kk * 64 + n2];
        u64p w2[4] = { pack2(w4.x, w4.x), pack2(w4.y, w4.y),
                       pack2(w4.z, w4.z), pack2(w4.w, w4.w) };
        ulonglong2 f = *(const ulonglong2*)&sh1[kk * 64 + pg * 4];
#pragma unroll
        for (int r = 0; r < 4; r++) {
            FMA2(acc2[r][0], f.x, w2[r], acc2[r][0]);
            FMA2(acc2[r][1], f.y, w2[r], acc2[r][1]);
        }
    }
#pragma unroll
    for (int r = 0; r < 4; r++) {
        float bias = rb2[n2 + r];
        float2 v0 = unpack2(acc2[r][0]), v1 = unpack2(acc2[r][1]);
        float* d = &sh2[(n2 + r) * 64 + pg * 4];
        d[0] = fmaxf(v0.x + bias, 0.f); d[1] = fmaxf(v0.y + bias, 0.f);
        d[2] = fmaxf(v1.x + bias, 0.f); d[3] = fmaxf(v1.y + bias, 0.f);
    }
    __syncthreads();

    // ---- layer 3 ----
    if (tid < 128) {
        int c = tid >> 6, pp = tid & 63;
        float a = rb3[c];
#pragma unroll 8
        for (int k = 0; k < 64; k++) a += sh2[k * 64 + pp] * sR3[c * 64 + k];
        float disp = tanhf(a);
        int ptg = p0 + pp;
        if (ptg < NPTS) {
            float iv = out[OUT_INIT + b * MDIM + ptg * 2 + c];
            float r = fminf(fmaxf(iv + 0.1f * disp, 0.f), 1.f);
            out[(b * NPTS + ptg) * 2 + c] = r;
        }
    }
}

// ---------------- 7) value head ----------------
__global__ void value_kernel(const float* __restrict__ V1, const float* __restrict__ vb1,
                             const float* __restrict__ V2, const float* __restrict__ vb2,
                             float* __restrict__ out) {
    extern __shared__ float sv[];
    float* spf  = sv;
    float* sV1  = sv + 128;
    float* sred = sv + 128 + 12800;
    int bp = blockIdx.x;
    int tid = threadIdx.x;
    if (tid < 100) spf[tid] = out[bp * 100 + tid];
    const float4* v4 = (const float4*)V1;
    float4* s4 = (float4*)sV1;
#pragma unroll
    for (int t = 0; t < 25; t++) s4[tid + t * 128] = v4[tid + t * 128];
    __syncthreads();
    float a = vb1[tid];
#pragma unroll 4
    for (int k = 0; k < 100; k++) a += spf[k] * sV1[tid * 100 + k];
    sred[tid] = fmaxf(a, 0.f) * V2[tid];
    __syncthreads();
#pragma unroll
    for (int s = 64; s > 0; s >>= 1) {
        if (tid < s) sred[tid] += sred[tid + s];
        __syncthreads();
    }
    if (tid == 0) out[OUT_V + bp] = 1.f / (1.f + expf(-(sred[0] + vb2[0])));
}

// ---------------- launch ----------------
extern "C" void kernel_launch(void* const* d_in, const int* in_sizes, int n_in,
                              void* d_out, int out_size) {
    const float* p4   = (const float*)d_in[0];
    const float* p2   = (const float*)d_in[1];
    const float* W1   = (const float*)d_in[3];
    const float* b1   = (const float*)d_in[4];
    const float* W2   = (const float*)d_in[5];
    const float* b2   = (const float*)d_in[6];
    const float* R1   = (const float*)d_in[7];
    const float* rb1  = (const float*)d_in[8];
    const float* R2   = (const float*)d_in[9];
    const float* rb2  = (const float*)d_in[10];
    const float* R3   = (const float*)d_in[11];
    const float* rb3  = (const float*)d_in[12];
    const float* V1   = (const float*)d_in[13];
    const float* vb1  = (const float*)d_in[14];
    const float* V2   = (const float*)d_in[15];
    const float* vb2  = (const float*)d_in[16];
    float* out = (float*)d_out;

    const int FC1_SMEM = (512 * FC1_SW_STRIDE + 128 * FC1_SF_STRIDE) * 4;   // 76800
    const int FC2_SMEM = (32 * 512 + 32 * FC2_SH_STRIDE) * 4;               // 67840
    const int RFN_SMEM = 20608 * 4;                                         // 82432

    cudaFuncSetAttribute(fc1_kernel,    cudaFuncAttributeMaxDynamicSharedMemorySize, FC1_SMEM);
    cudaFuncSetAttribute(fc2_kernel,    cudaFuncAttributeMaxDynamicSharedMemorySize, FC2_SMEM);
    cudaFuncSetAttribute(gather_kernel, cudaFuncAttributeMaxDynamicSharedMemorySize, 65536);
    cudaFuncSetAttribute(refine_kernel, cudaFuncAttributeMaxDynamicSharedMemorySize, RFN_SMEM);
    cudaFuncSetAttribute(value_kernel,  cudaFuncAttributeMaxDynamicSharedMemorySize, 52224);

    pool_kernel<<<1186, 256>>>(p4, R1, R2);
    fc1_kernel<<<dim3(128, 2), 256, FC1_SMEM>>>(W1);
    reduce_h_kernel<<<512, 256>>>(b1);
    fc2_kernel<<<dim3(4, 32), 256, FC2_SMEM>>>(W2);
    epi_kernel<<<1000, 256>>>(b2, out);
    gather_kernel<<<4096, 256, 65536>>>(p2, out);
    refine_kernel<<<dim3(16, 16), 256, RFN_SMEM>>>(rb1, rb2, R3, rb3, out);
    value_kernel<<<320, 128, 52224>>>(V1, vb1, V2, vb2, out);
}

// round 5
// speedup vs baseline: 2.0408x; 1.1036x over previous
#include <cuda_runtime.h>
#include <cuda_bf16.h>
#include <math.h>

// Problem constants
#define BB 16
#define NPTS 1000
#define KDIM 16384         // C*64 (fc1 input)
#define H1DIM 1024
#define MDIM 2000          // P*K*2
#define FDIM 258

// Output layout: refined [32000] @0, v [320] @32000, init [32000] @32320
#define OUT_V    32000
#define OUT_INIT 32320

// ---------------- packed f32x2 helpers (SASS FFMA2 path) ----------------
typedef unsigned long long u64p;
__device__ __forceinline__ u64p pack2(float lo, float hi) {
    u64p r; asm("mov.b64 %0, {%1,%2};" : "=l"(r) : "f"(lo), "f"(hi)); return r;
}
__device__ __forceinline__ float2 unpack2(u64p v) {
    float2 r; asm("mov.b64 {%0,%1}, %2;" : "=f"(r.x), "=f"(r.y) : "l"(v)); return r;
}
#define FMA2(d, a, b, c) asm("fma.rn.f32x2 %0, %1, %2, %3;" : "=l"(d) : "l"(a), "l"(b), "l"(c))

// ---------------- scratch ----------------
__device__ float g_flat[BB * KDIM];                    // pooled [b][k]
__device__ float g_hpart[128 * BB * H1DIM];            // fc1 partials [ks][b][n]
__device__ float g_h[BB * H1DIM];                      // relu(h) [b][n]
__device__ float g_logpart[64 * BB * 2048];            // fc2 partials [ks][b][m pad]
__device__ float g_feat[(size_t)BB * FDIM * 1024];     // [b][k(258)][pt pad 1024]
__device__ float g_R1t[FDIM * 128];                    // R1^T [k][n]
__device__ float g_R2t[128 * 64];                      // R2^T [k][n]

// ---------------- 1) avg pool (+ prep transposes merged) ----------------
__global__ void pool_kernel(const float* __restrict__ p4,
                            const float* __restrict__ R1, const float* __restrict__ R2) {
    cudaTriggerProgrammaticLaunchCompletion();  // successor prologue reads only inputs
    if (blockIdx.x < 1024) {
        int idx = blockIdx.x * 256 + threadIdx.x;
        int j = idx & 7, i = (idx >> 3) & 7;
        int bc = idx >> 6;
        const float* base = p4 + (size_t)bc * 1024 + i * 128 + j * 4;
        float s = 0.f;
#pragma unroll
        for (int di = 0; di < 4; di++) {
            float4 v = *(const float4*)(base + di * 32);
            s += v.x + v.y + v.z + v.w;
        }
        g_flat[idx] = s * (1.0f / 16.0f);
    } else {
        int idx = (blockIdx.x - 1024) * 256 + threadIdx.x;
        if (idx < FDIM * 128) {
            int k = idx >> 7, n = idx & 127;
            g_R1t[idx] = R1[n * FDIM + k];
        } else if (idx < FDIM * 128 + 128 * 64) {
            int i = idx - FDIM * 128;
            int k = i >> 6, n = i & 63;
            g_R2t[i] = R2[n * 128 + k];
        }
    }
}

// ---------------- 2) FC1: 512 n x 128 k-slice per block, grid (128,2) ----------------
// thread: rows {tid, tid+256} x 16b. smem 76800 B.
#define FC1_SW_STRIDE 33
#define FC1_SF_STRIDE 18
__global__ void fc1_kernel(const float* __restrict__ W1) {
    extern __shared__ float sm1[];
    float* sW = sm1;                         // [512 n][33]
    float* sf = sm1 + 512 * FC1_SW_STRIDE;   // [128 k][18]
    int tid = threadIdx.x;
    int ks = blockIdx.x;
    int k0 = ks * 128;
    int nb = blockIdx.y * 512;

    // --- pre-sync prologue: W1 chunk 0 -> smem (input only; overlaps pool) ---
#pragma unroll
    for (int t = 0; t < 16; t++) {
        int f = tid + t * 256;
        int r = f >> 3, c = f & 7;
        float4 v = *(const float4*)&W1[(size_t)(nb + r) * KDIM + k0 + c * 4];
        float* d = &sW[r * FC1_SW_STRIDE + c * 4];
        d[0] = v.x; d[1] = v.y; d[2] = v.z; d[3] = v.w;
    }
    cudaGridDependencySynchronize();
    cudaTriggerProgrammaticLaunchCompletion();

    // flat slice [128 k][16 b]
#pragma unroll
    for (int t = 0; t < 8; t++) {
        int e = tid + t * 256;
        int b = e >> 7, kk = e & 127;
        sf[kk * FC1_SF_STRIDE + b] = g_flat[b * KDIM + k0 + kk];
    }
    __syncthreads();

    u64p acc[2][8];
#pragma unroll
    for (int r = 0; r < 2; r++)
#pragma unroll
        for (int j = 0; j < 8; j++) acc[r][j] = 0;

    for (int kc = 0; kc < 128; kc += 32) {
#pragma unroll 4
        for (int kk = 0; kk < 32; kk++) {
            float w0 = sW[tid * FC1_SW_STRIDE + kk];
            float w1 = sW[(tid + 256) * FC1_SW_STRIDE + kk];
            u64p w20 = pack2(w0, w0), w21 = pack2(w1, w1);
            const u64p* fl = (const u64p*)&sf[(kc + kk) * FC1_SF_STRIDE];
#pragma unroll
            for (int j = 0; j < 8; j++) {
                u64p f = fl[j];
                FMA2(acc[0][j], f, w20, acc[0][j]);
                FMA2(acc[1][j], f, w21, acc[1][j]);
            }
        }
        if (kc < 96) {
            __syncthreads();
#pragma unroll
            for (int t = 0; t < 16; t++) {
                int f = tid + t * 256;
                int r = f >> 3, c = f & 7;
                float4 v = *(const float4*)&W1[(size_t)(nb + r) * KDIM + k0 + kc + 32 + c * 4];
                float* d = &sW[r * FC1_SW_STRIDE + c * 4];
                d[0] = v.x; d[1] = v.y; d[2] = v.z; d[3] = v.w;
            }
            __syncthreads();
        }
    }
#pragma unroll
    for (int r = 0; r < 2; r++) {
        int n = nb + tid + r * 256;
#pragma unroll
        for (int j = 0; j < 8; j++) {
            float2 v = unpack2(acc[r][j]);
            g_hpart[(ks * 16 + 2 * j + 0) * H1DIM + n] = v.x;
            g_hpart[(ks * 16 + 2 * j + 1) * H1DIM + n] = v.y;
        }
    }
}

// ---------------- 2b) reduce 128 partials: 8 lanes/elem + shuffle ----------------
__global__ void reduce_h_kernel(const float* __restrict__ b1) {
    cudaGridDependencySynchronize();
    cudaTriggerProgrammaticLaunchCompletion();
    int gid = blockIdx.x * 256 + threadIdx.x;   // 0..131071
    int e = gid >> 3;                            // 0..16383 = b*1024+n
    int r = gid & 7;
    float s = 0.f;
#pragma unroll
    for (int t = 0; t < 16; t++) s += g_hpart[(r + t * 8) * (BB * H1DIM) + e];
    s += __shfl_xor_sync(0xFFFFFFFFu, s, 1);
    s += __shfl_xor_sync(0xFFFFFFFFu, s, 2);
    s += __shfl_xor_sync(0xFFFFFFFFu, s, 4);
    if (r == 0) g_h[e] = fmaxf(s + b1[e & 1023], 0.f);
}

// ---------------- 3) FC2: 512 m-tile x 16 k-slice, grid (4,64) ----------------
#define FC2_SH_STRIDE 18
__global__ void fc2_kernel(const float* __restrict__ W2) {
    extern __shared__ float sm2[];
    float* sWt = sm2;                      // [16 k][512 m]
    float* sh  = sm2 + 16 * 512;           // [16 k][18]
    int tid = threadIdx.x;
    int m0 = blockIdx.x * 512;
    int ks = blockIdx.y;
    int k0 = ks * 16;
    int m = m0 + tid * 2;

    // --- pre-sync prologue: W2 tile -> smem transposed (input only) ---
#pragma unroll
    for (int mi = 0; mi < 2; mi++) {
        int mr = m + mi;
        if (mr < MDIM) {
#pragma unroll
            for (int c = 0; c < 4; c++) {
                float4 v = *(const float4*)&W2[(size_t)mr * H1DIM + k0 + c * 4];
                sWt[(c * 4 + 0) * 512 + tid * 2 + mi] = v.x;
                sWt[(c * 4 + 1) * 512 + tid * 2 + mi] = v.y;
                sWt[(c * 4 + 2) * 512 + tid * 2 + mi] = v.z;
                sWt[(c * 4 + 3) * 512 + tid * 2 + mi] = v.w;
            }
        } else {
#pragma unroll
            for (int kk = 0; kk < 16; kk++) sWt[kk * 512 + tid * 2 + mi] = 0.f;
        }
    }
    cudaGridDependencySynchronize();
    cudaTriggerProgrammaticLaunchCompletion();

    // h slice [16 k][16 b]: one elem per thread
    {
        int kk = tid >> 4, b = tid & 15;
        sh[kk * FC2_SH_STRIDE + b] = g_h[b * H1DIM + k0 + kk];
    }
    __syncthreads();

    u64p acc[2][8];
#pragma unroll
    for (int mi = 0; mi < 2; mi++)
#pragma unroll
        for (int j = 0; j < 8; j++) acc[mi][j] = 0;

#pragma unroll 4
    for (int kk = 0; kk < 16; kk++) {
        float w0 = sWt[kk * 512 + tid * 2 + 0];
        float w1 = sWt[kk * 512 + tid * 2 + 1];
        u64p w20 = pack2(w0, w0), w21 = pack2(w1, w1);
        const u64p* fl = (const u64p*)&sh[kk * FC2_SH_STRIDE];
#pragma unroll
        for (int j = 0; j < 8; j++) {
            u64p f = fl[j];
            FMA2(acc[0][j], f, w20, acc[0][j]);
            FMA2(acc[1][j], f, w21, acc[1][j]);
        }
    }
#pragma unroll
    for (int mi = 0; mi < 2; mi++) {
        int mr = m + mi;
        if (mr < MDIM) {
#pragma unroll
            for (int j = 0; j < 8; j++) {
                float2 v = unpack2(acc[mi][j]);
                g_logpart[(ks * 16 + 2 * j + 0) * 2048 + mr] = v.x;
                g_logpart[(ks * 16 + 2 * j + 1) * 2048 + mr] = v.y;
            }
        }
    }
}

// ---------------- 4) epilogue: shuffle-reduce 64 partials -> sigmoid ----------------
__global__ void epi_kernel(const float* __restrict__ b2, float* __restrict__ out) {
    cudaGridDependencySynchronize();
    cudaTriggerProgrammaticLaunchCompletion();
    int gid = blockIdx.x * 256 + threadIdx.x;   // 0..255999
    int e = gid >> 3;                            // 0..31999
    int r = gid & 7;
    int b = e / MDIM, m = e - b * MDIM;
    float s = 0.f;
#pragma unroll
    for (int t = 0; t < 8; t++) s += g_logpart[((r + t * 8) * 16 + b) * 2048 + m];
    s += __shfl_xor_sync(0xFFFFFFFFu, s, 1);
    s += __shfl_xor_sync(0xFFFFFFFFu, s, 2);
    s += __shfl_xor_sync(0xFFFFFFFFu, s, 4);
    if (r == 0) {
        float v = 1.f / (1.f + expf(-(s + b2[m])));
        out[OUT_INIT + b * MDIM + m] = v;
        int pt = m >> 1, c = m & 1;
        g_feat[((size_t)b * FDIM + 256 + c) * 1024 + pt] = v;
    }
}

// ---------------- 5) bilinear gather ----------------
__global__ void gather_kernel(const float* __restrict__ p2, const float* __restrict__ out) {
    extern __shared__ float img[];               // 64KB
    int bc = blockIdx.x;
    int b = bc >> 8;
    int tid = threadIdx.x;

    // --- pre-sync prologue: image -> smem (input only; overlaps epi) ---
    const float4* src = (const float4*)(p2 + (size_t)bc * 16384);
    float4* di = (float4*)img;
#pragma unroll
    for (int t = 0; t < 16; t++) di[tid + t * 256] = src[tid + t * 256];
    cudaGridDependencySynchronize();
    cudaTriggerProgrammaticLaunchCompletion();

    const float* initp = out + OUT_INIT + b * MDIM;
    float px[4], py[4];
#pragma unroll
    for (int t = 0; t < 4; t++) {
        int pt = tid + t * 256;
        if (pt < NPTS) { px[t] = initp[pt * 2 + 0]; py[t] = initp[pt * 2 + 1]; }
    }
    __syncthreads();

    float* frow = &g_feat[((size_t)b * FDIM + (bc & 255)) * 1024];
#pragma unroll
    for (int t = 0; t < 4; t++) {
        int pt = tid + t * 256;
        if (pt < NPTS) {
            float x = px[t] * 128.f - 0.5f;
            float y = py[t] * 128.f - 0.5f;
            float x0f = floorf(x), y0f = floorf(y);
            int x0 = (int)x0f, y0 = (int)y0f;
            float wx = x - x0f, wy = y - y0f;
            bool xv0 = (x0 >= 0) & (x0 <= 127);
            bool xv1 = (x0 + 1 >= 0) & (x0 + 1 <= 127);
            bool yv0 = (y0 >= 0) & (y0 <= 127);
            bool yv1 = (y0 + 1 >= 0) & (y0 + 1 <= 127);
            int x0c = min(max(x0, 0), 127), x1c = min(max(x0 + 1, 0), 127);
            int y0c = min(max(y0, 0), 127), y1c = min(max(y0 + 1, 0), 127);
            float v00 = (xv0 && yv0) ? img[y0c * 128 + x0c] : 0.f;
            float v10 = (xv1 && yv0) ? img[y0c * 128 + x1c] : 0.f;
            float v01 = (xv0 && yv1) ? img[y1c * 128 + x0c] : 0.f;
            float v11 = (xv1 && yv1) ? img[y1c * 128 + x1c] : 0.f;
            frow[pt] = v00 * (1.f - wx) * (1.f - wy) + v10 * wx * (1.f - wy)
                     + v01 * (1.f - wx) * wy        + v11 * wx * wy;
        }
    }
}

// ---------------- 6) refine MLP: streamed k-chunks, 82432 B smem ----------------
__global__ void refine_kernel(const float* __restrict__ rb1,
                              const float* __restrict__ rb2,
                              const float* __restrict__ R3, const float* __restrict__ rb3,
                              float* __restrict__ out) {
    extern __shared__ float smr[];
    float* sh1    = smr;            // [128][64]
    float* sfeatc = smr + 8192;     // [32][64]   (layer1)  | sR2t overlays @8192 (layer2)
    float* sR1    = smr + 10240;    // [32][128]  (layer1)
    float* scoord = smr + 14336;    // [2][64]
    float* sR2t   = smr + 8192;     // [128][64]  (layer2)
    float* sh2    = smr + 16384;    // [64][64]
    float* sR3    = smr + 20480;    // [128]

    int tid = threadIdx.x;
    int b = blockIdx.y;
    int p0 = blockIdx.x * 64;
    int pg = tid & 15;
    int ng = tid >> 4;
    int n0 = ng * 8;

    // --- pre-sync prologue: coord rows (epi output = N-2, safe) + R3 (input) ---
    if (tid < 128) {
        scoord[tid] = g_feat[((size_t)b * FDIM + 256 + (tid >> 6)) * 1024 + p0 + (tid & 63)];
        sR3[tid] = R3[tid];
    }
    cudaGridDependencySynchronize();
    cudaTriggerProgrammaticLaunchCompletion();

    u64p acc[8][2];
#pragma unroll
    for (int r = 0; r < 8; r++) { acc[r][0] = 0; acc[r][1] = 0; }

    for (int kc = 0; kc < 256; kc += 32) {
        __syncthreads();
#pragma unroll
        for (int t = 0; t < 2; t++) {
            int f = tid + t * 256;
            int row = f >> 4, col = f & 15;
            ((float4*)sfeatc)[row * 16 + col] =
                *(const float4*)&g_feat[((size_t)b * FDIM + kc + row) * 1024 + p0 + col * 4];
        }
#pragma unroll
        for (int t = 0; t < 4; t++) {
            int f = tid + t * 256;
            ((float4*)sR1)[f] = ((const float4*)(g_R1t + kc * 128))[f];
        }
        __syncthreads();
#pragma unroll 2
        for (int kk = 0; kk < 32; kk++) {
            u64p w2[8];
#pragma unroll
            for (int r = 0; r < 8; r += 4) {
                float4 w4 = *(const float4*)&sR1[kk * 128 + n0 + r];
                w2[r + 0] = pack2(w4.x, w4.x); w2[r + 1] = pack2(w4.y, w4.y);
                w2[r + 2] = pack2(w4.z, w4.z); w2[r + 3] = pack2(w4.w, w4.w);
            }
            ulonglong2 f = *(const ulonglong2*)&sfeatc[kk * 64 + pg * 4];
#pragma unroll
            for (int r = 0; r < 8; r++) {
                FMA2(acc[r][0], f.x, w2[r], acc[r][0]);
                FMA2(acc[r][1], f.y, w2[r], acc[r][1]);
            }
        }
    }
#pragma unroll
    for (int kr = 0; kr < 2; kr++) {
        ulonglong2 f = *(const ulonglong2*)&scoord[kr * 64 + pg * 4];
#pragma unroll
        for (int r = 0; r < 8; r++) {
            float w = g_R1t[(256 + kr) * 128 + n0 + r];
            u64p w2 = pack2(w, w);
            FMA2(acc[r][0], f.x, w2, acc[r][0]);
            FMA2(acc[r][1], f.y, w2, acc[r][1]);
        }
    }
#pragma unroll
    for (int r = 0; r < 8; r++) {
        float bias = rb1[n0 + r];
        float2 v0 = unpack2(acc[r][0]), v1 = unpack2(acc[r][1]);
        float* d = &sh1[(n0 + r) * 64 + pg * 4];
        d[0] = fmaxf(v0.x + bias, 0.f); d[1] = fmaxf(v0.y + bias, 0.f);
        d[2] = fmaxf(v1.x + bias, 0.f); d[3] = fmaxf(v1.y + bias, 0.f);
    }
    __syncthreads();

    // ---- layer 2 ----
#pragma unroll
    for (int t = 0; t < 8; t++) {
        int f = tid + t * 256;
        ((float4*)sR2t)[f] = ((const float4*)g_R2t)[f];
    }
    __syncthreads();

    int n2 = ng * 4;
    u64p acc2[4][2];
#pragma unroll
    for (int r = 0; r < 4; r++) { acc2[r][0] = 0; acc2[r][1] = 0; }
#pragma unroll 2
    for (int kk = 0; kk < 128; kk++) {
        float4 w4 = *(const float4*)&sR2t[kk * 64 + n2];
        u64p w2[4] = { pack2(w4.x, w4.x), pack2(w4.y, w4.y),
                       pack2(w4.z, w4.z), pack2(w4.w, w4.w) };
        ulonglong2 f = *(const ulonglong2*)&sh1[kk * 64 + pg * 4];
#pragma unroll
        for (int r = 0; r < 4; r++) {
            FMA2(acc2[r][0], f.x, w2[r], acc2[r][0]);
            FMA2(acc2[r][1], f.y, w2[r], acc2[r][1]);
        }
    }
#pragma unroll
    for (int r = 0; r < 4; r++) {
        float bias = rb2[n2 + r];
        float2 v0 = unpack2(acc2[r][0]), v1 = unpack2(acc2[r][1]);
        float* d = &sh2[(n2 + r) * 64 + pg * 4];
        d[0] = fmaxf(v0.x + bias, 0.f); d[1] = fmaxf(v0.y + bias, 0.f);
        d[2] = fmaxf(v1.x + bias, 0.f); d[3] = fmaxf(v1.y + bias, 0.f);
    }
    __syncthreads();

    if (tid < 128) {
        int c = tid >> 6, pp = tid & 63;
        float a = rb3[c];
#pragma unroll 8
        for (int k = 0; k < 64; k++) a += sh2[k * 64 + pp] * sR3[c * 64 + k];
        float disp = tanhf(a);
        int ptg = p0 + pp;
        if (ptg < NPTS) {
            float iv = out[OUT_INIT + b * MDIM + ptg * 2 + c];
            float r = fminf(fmaxf(iv + 0.1f * disp, 0.f), 1.f);
            out[(b * NPTS + ptg) * 2 + c] = r;
        }
    }
}

// ---------------- 7) value head ----------------
__global__ void value_kernel(const float* __restrict__ V1, const float* __restrict__ vb1,
                             const float* __restrict__ V2, const float* __restrict__ vb2,
                             float* __restrict__ out) {
    extern __shared__ float sv[];
    float* spf  = sv;
    float* sV1  = sv + 128;
    float* sred = sv + 128 + 12800;
    int bp = blockIdx.x;
    int tid = threadIdx.x;

    // --- pre-sync prologue: V1 -> smem (input only; overlaps refine tail) ---
    const float4* v4 = (const float4*)V1;
    float4* s4 = (float4*)sV1;
#pragma unroll
    for (int t = 0; t < 25; t++) s4[tid + t * 128] = v4[tid + t * 128];
    cudaGridDependencySynchronize();

    if (tid < 100) spf[tid] = out[bp * 100 + tid];
    __syncthreads();
    float a = vb1[tid];
#pragma unroll 4
    for (int k = 0; k < 100; k++) a += spf[k] * sV1[tid * 100 + k];
    sred[tid] = fmaxf(a, 0.f) * V2[tid];
    __syncthreads();
#pragma unroll
    for (int s = 64; s > 0; s >>= 1) {
        if (tid < s) sred[tid] += sred[tid + s];
        __syncthreads();
    }
    if (tid == 0) out[OUT_V + bp] = 1.f / (1.f + expf(-(sred[0] + vb2[0])));
}

// ---------------- launch ----------------
extern "C" void kernel_launch(void* const* d_in, const int* in_sizes, int n_in,
                              void* d_out, int out_size) {
    const float* p4   = (const float*)d_in[0];
    const float* p2   = (const float*)d_in[1];
    const float* W1   = (const float*)d_in[3];
    const float* b1   = (const float*)d_in[4];
    const float* W2   = (const float*)d_in[5];
    const float* b2   = (const float*)d_in[6];
    const float* R1   = (const float*)d_in[7];
    const float* rb1  = (const float*)d_in[8];
    const float* R2   = (const float*)d_in[9];
    const float* rb2  = (const float*)d_in[10];
    const float* R3   = (const float*)d_in[11];
    const float* rb3  = (const float*)d_in[12];
    const float* V1   = (const float*)d_in[13];
    const float* vb1  = (const float*)d_in[14];
    const float* V2   = (const float*)d_in[15];
    const float* vb2  = (const float*)d_in[16];
    float* out = (float*)d_out;

    const int FC1_SMEM = (512 * FC1_SW_STRIDE + 128 * FC1_SF_STRIDE) * 4;   // 76800
    const int FC2_SMEM = (16 * 512 + 16 * FC2_SH_STRIDE) * 4;               // 33920
    const int RFN_SMEM = 20608 * 4;                                         // 82432

    cudaFuncSetAttribute(fc1_kernel,    cudaFuncAttributeMaxDynamicSharedMemorySize, FC1_SMEM);
    cudaFuncSetAttribute(fc2_kernel,    cudaFuncAttributeMaxDynamicSharedMemorySize, FC2_SMEM);
    cudaFuncSetAttribute(gather_kernel, cudaFuncAttributeMaxDynamicSharedMemorySize, 65536);
    cudaFuncSetAttribute(refine_kernel, cudaFuncAttributeMaxDynamicSharedMemorySize, RFN_SMEM);
    cudaFuncSetAttribute(value_kernel,  cudaFuncAttributeMaxDynamicSharedMemorySize, 52224);

    cudaLaunchAttribute pdl[1];
    pdl[0].id = cudaLaunchAttributeProgrammaticStreamSerialization;
    pdl[0].val.programmaticStreamSerializationAllowed = 1;

    // 1) pool (plain launch; triggers early in-body)
    pool_kernel<<<1186, 256>>>(p4, R1, R2);

    cudaLaunchConfig_t cfg = {};
    cfg.blockDim = {256, 1, 1};
    cfg.stream = 0;
    cfg.attrs = pdl;
    cfg.numAttrs = 1;

    // 2) fc1
    cfg.gridDim = {128, 2, 1};  cfg.dynamicSmemBytes = FC1_SMEM;
    cudaLaunchKernelEx(&cfg, fc1_kernel, W1);
    // 2b) reduce_h
    cfg.gridDim = {512, 1, 1};  cfg.dynamicSmemBytes = 0;
    cudaLaunchKernelEx(&cfg, reduce_h_kernel, b1);
    // 3) fc2
    cfg.gridDim = {4, 64, 1};   cfg.dynamicSmemBytes = FC2_SMEM;
    cudaLaunchKernelEx(&cfg, fc2_kernel, W2);
    // 4) epi
    cfg.gridDim = {1000, 1, 1}; cfg.dynamicSmemBytes = 0;
    cudaLaunchKernelEx(&cfg, epi_kernel, b2, out);
    // 5) gather
    cfg.gridDim = {4096, 1, 1}; cfg.dynamicSmemBytes = 65536;
    cudaLaunchKernelEx(&cfg, gather_kernel, p2, out);
    // 6) refine
    cfg.gridDim = {16, 16, 1};  cfg.dynamicSmemBytes = RFN_SMEM;
    cudaLaunchKernelEx(&cfg, refine_kernel, rb1, rb2, R3, rb3, out);
    // 7) value
    cfg.gridDim = {320, 1, 1};  cfg.blockDim = {128, 1, 1}; cfg.dynamicSmemBytes = 52224;
    cudaLaunchKernelEx(&cfg, value_kernel, V1, vb1, V2, vb2, out);
}